// round 15
// baseline (speedup 1.0000x reference)
#include <cuda_runtime.h>
#include <cuda_bf16.h>
#include <mma.h>

using namespace nvcuda;
typedef __nv_bfloat16 bf16;

// Problem constants
#define DMODEL 256
#define NHEAD  4
#define HD     64
#define NLAYER 8
#define DFF    1024
#define VOCAB  100
#define LT     256
#define BBATCH 2
#define FHH    32
#define FWW    256
#define SMEMN  (FHH*FWW)      // 8192
#define LB     (LT*BBATCH)    // 512
#define SBR    (SMEMN*BBATCH) // 16384
#define BNH    (BBATCH*NHEAD) // 8
#define LDQ    (BBATCH*DMODEL)// 512
#define QT     4              // q-tiles of 64 over LT

#define CKV_L   ((size_t)2*SBR*DMODEL)          // per-layer [ck|cv] elements
#define CKVB_PL ((size_t)NLAYER*CKV_L)          // plane offset (hi->lo)

#define LN10K 9.210340371976184f

// -------- scratch (device globals, allocation-free) --------
__device__ float g_mem[SBR*DMODEL];                    // 16 MB
__device__ __align__(16) bf16 g_ckvb[2*NLAYER*2*SBR*DMODEL];  // 268 MB bf16 hi/lo planes
__device__ float g_qkv[3*LB*DMODEL];
__device__ float g_tgt[LB*DMODEL];
__device__ float g_ao [LB*DMODEL];
__device__ float g_ffh[LB*DFF];
__device__ float g_part[4*1024*1024];                  // split-K / flash partials
__device__ float g_partl[BNH*QT*16*64];                // flash row-sum partials

__device__ __forceinline__ void split1(float v, bf16& h, bf16& l) {
    h = __float2bfloat16(v);
    l = __float2bfloat16(v - __bfloat162float(h));
}

// -------- memory tensor: features + 2D PE --------
__global__ void mem_kernel(const float* __restrict__ features, float* __restrict__ mem) {
    int idx = blockIdx.x * 256 + threadIdx.x;
    int c   = idx & (DMODEL-1);
    int row = idx >> 8;
    int b   = row & (BBATCH-1);
    int s   = row >> 1;
    int h   = s / FWW;
    int w   = s % FWW;
    float pe;
    if (c < DMODEL/2) {
        int e = c & ~1;
        float dv = __expf(-(float)e / (float)DMODEL * LN10K);
        float arg = (float)h * dv;
        pe = (c & 1) ? cosf(arg) : sinf(arg);
    } else {
        int e = (c - DMODEL/2) & ~1;
        float dv = __expf(-(float)e / (float)DMODEL * LN10K);
        float arg = (float)w * dv;
        pe = (c & 1) ? cosf(arg) : sinf(arg);
    }
    mem[idx] = features[(((size_t)b*DMODEL + c)*FHH + h)*FWW + w] + pe;
}

// -------- embedding + 1D PE --------
__global__ void embed_kernel(const int* __restrict__ tokens, const float* __restrict__ emb,
                             float* __restrict__ tgt) {
    int idx = blockIdx.x * 256 + threadIdx.x;
    int c   = idx & (DMODEL-1);
    int row = idx >> 8;
    int l   = row >> 1;
    int tok = tokens[row];
    int e = c & ~1;
    float dv = __expf(-(float)e / (float)DMODEL * LN10K);
    float arg = (float)l * dv;
    float pe = (c & 1) ? cosf(arg) : sinf(arg);
    tgt[idx] = emb[(size_t)tok*DMODEL + c] + pe;
}

// ============================================================================
// bf16x3 NT GEMM (R9/R11-proven, BK=16 single buffer).
// ksplit==1 epilogue: writes Cf (fp32) if non-null and/or Cb (bf16 hi/lo planes).
// ============================================================================
__global__ __launch_bounds__(256) void wgemm_nt(
    const float* __restrict__ A, int lda, int aB,
    const float* __restrict__ Bm, int ldb, int bB,
    const float* __restrict__ bias, int biasB,
    float* __restrict__ Cf, bf16* __restrict__ Cb, size_t cPlane,
    int ldc, int cB,
    int M, int N, int K, int ksplit, float scale, int relu)
{
    __shared__ __align__(16) char smem_u[64*132*4];
    bf16 (*Ah)[24] = (bf16(*)[24])smem_u;
    bf16 (*Al)[24] = (bf16(*)[24])(smem_u + 3072);
    bf16 (*Bh)[24] = (bf16(*)[24])(smem_u + 6144);
    bf16 (*Bl)[24] = (bf16(*)[24])(smem_u + 12288);
    float (*Os)[132] = (float(*)[132])smem_u;

    int ks = blockIdx.z % ksplit, batch = blockIdx.z / ksplit;
    A  += (size_t)batch * aB;
    Bm += (size_t)batch * bB;
    if (ksplit > 1) {
        Cf += (size_t)blockIdx.z * M * N;
    } else {
        if (Cf) Cf += (size_t)batch * cB;
        if (Cb) Cb += (size_t)batch * cB;
        if (bias) bias += (size_t)batch * biasB;
    }
    int row0 = blockIdx.y * 64, col0 = blockIdx.x * 128;
    int tid = threadIdx.x;
    int wid = tid >> 5;
    int wm = wid >> 2, wn = wid & 3;

    wmma::fragment<wmma::accumulator, 16,16,16, float> cf[2][2];
    #pragma unroll
    for (int i=0;i<2;i++)
        #pragma unroll
        for (int j=0;j<2;j++) wmma::fill_fragment(cf[i][j], 0.0f);

    int kbeg = ks * (K/ksplit), kend = kbeg + K/ksplit;
    int am = tid >> 2, ac = (tid & 3) * 4;

    for (int k0 = kbeg; k0 < kend; k0 += 16) {
        {
            float4 va = *(const float4*)&A[(size_t)(row0+am)*lda + k0 + ac];
            split1(va.x, Ah[am][ac  ], Al[am][ac  ]);
            split1(va.y, Ah[am][ac+1], Al[am][ac+1]);
            split1(va.z, Ah[am][ac+2], Al[am][ac+2]);
            split1(va.w, Ah[am][ac+3], Al[am][ac+3]);
            float4 v0 = *(const float4*)&Bm[(size_t)(col0+am)*ldb + k0 + ac];
            split1(v0.x, Bh[am][ac  ], Bl[am][ac  ]);
            split1(v0.y, Bh[am][ac+1], Bl[am][ac+1]);
            split1(v0.z, Bh[am][ac+2], Bl[am][ac+2]);
            split1(v0.w, Bh[am][ac+3], Bl[am][ac+3]);
            float4 v1 = *(const float4*)&Bm[(size_t)(col0+am+64)*ldb + k0 + ac];
            split1(v1.x, Bh[am+64][ac  ], Bl[am+64][ac  ]);
            split1(v1.y, Bh[am+64][ac+1], Bl[am+64][ac+1]);
            split1(v1.z, Bh[am+64][ac+2], Bl[am+64][ac+2]);
            split1(v1.w, Bh[am+64][ac+3], Bl[am+64][ac+3]);
        }
        __syncthreads();
        wmma::fragment<wmma::matrix_a, 16,16,16, bf16, wmma::row_major> ah[2], al[2];
        wmma::fragment<wmma::matrix_b, 16,16,16, bf16, wmma::col_major> bh[2], bl[2];
        #pragma unroll
        for (int i=0;i<2;i++) {
            wmma::load_matrix_sync(ah[i], &Ah[wm*32 + i*16][0], 24);
            wmma::load_matrix_sync(al[i], &Al[wm*32 + i*16][0], 24);
        }
        #pragma unroll
        for (int j=0;j<2;j++) {
            wmma::load_matrix_sync(bh[j], &Bh[wn*32 + j*16][0], 24);
            wmma::load_matrix_sync(bl[j], &Bl[wn*32 + j*16][0], 24);
        }
        #pragma unroll
        for (int i=0;i<2;i++)
            #pragma unroll
            for (int j=0;j<2;j++) {
                wmma::mma_sync(cf[i][j], ah[i], bh[j], cf[i][j]);
                wmma::mma_sync(cf[i][j], ah[i], bl[j], cf[i][j]);
                wmma::mma_sync(cf[i][j], al[i], bh[j], cf[i][j]);
            }
        __syncthreads();
    }

    #pragma unroll
    for (int i=0;i<2;i++)
        #pragma unroll
        for (int j=0;j<2;j++)
            wmma::store_matrix_sync(&Os[wm*32+i*16][wn*32+j*16], cf[i][j], 132, wmma::mem_row_major);
    __syncthreads();

    #pragma unroll
    for (int it = 0; it < 8; it++) {
        int idx = it*256 + tid;
        int m = idx >> 5;
        int c4 = (idx & 31) * 4;
        float4 v = *(float4*)&Os[m][c4];
        if (ksplit == 1) {
            if (bias) {
                v.x += bias[col0+c4];   v.y += bias[col0+c4+1];
                v.z += bias[col0+c4+2]; v.w += bias[col0+c4+3];
            }
            v.x *= scale; v.y *= scale; v.z *= scale; v.w *= scale;
            if (relu) {
                v.x = fmaxf(v.x, 0.f); v.y = fmaxf(v.y, 0.f);
                v.z = fmaxf(v.z, 0.f); v.w = fmaxf(v.w, 0.f);
            }
            size_t o = (size_t)(row0+m)*ldc + col0 + c4;
            if (Cf) *(float4*)&Cf[o] = v;
            if (Cb) {
                bf16 hv[4], lv[4];
                split1(v.x, hv[0], lv[0]); split1(v.y, hv[1], lv[1]);
                split1(v.z, hv[2], lv[2]); split1(v.w, hv[3], lv[3]);
                *(uint2*)&Cb[o] = *(uint2*)hv;
                *(uint2*)&Cb[cPlane + o] = *(uint2*)lv;
            }
        } else {
            *(float4*)&Cf[(size_t)(row0+m)*N + col0 + c4] = v;
        }
    }
}

// -------- split-K reduce (plain fp32 out) --------
__global__ void reduce_sk(const float* __restrict__ P, float* __restrict__ C,
                          int ldc, int cB, int M, int N, int ksplit,
                          const float* __restrict__ bias, int biasB, int relu)
{
    int idx = blockIdx.x * 256 + threadIdx.x;
    int n = idx % N;
    int mb = idx / N;
    int m = mb % M;
    int batch = mb / M;
    const float* p = P + ((size_t)batch*ksplit)*M*N + (size_t)m*N + n;
    float s = 0.0f;
    for (int ksi = 0; ksi < ksplit; ksi++) s += p[(size_t)ksi*M*N];
    if (bias) s += bias[(size_t)batch*biasB + n];
    if (relu) s = fmaxf(s, 0.0f);
    C[(size_t)batch*cB + (size_t)m*ldc + n] = s;
}

// -------- FUSED: split-K reduce + bias + residual + LayerNorm (in-place tgt) ----
__global__ void reduce_ln(const float* __restrict__ P, int ksplit,
                          const float* __restrict__ bias,
                          float* __restrict__ tgt,
                          const float* __restrict__ g, const float* __restrict__ b)
{
    __shared__ float shm[8];
    int row = blockIdx.x, c = threadIdx.x;
    size_t idx = (size_t)row * DMODEL + c;
    float s = 0.0f;
    for (int ksi = 0; ksi < ksplit; ksi++) s += P[(size_t)ksi*LB*DMODEL + idx];
    s += bias[c];
    float x = tgt[idx] + s;

    float t = x;
    for (int o = 16; o; o >>= 1) t += __shfl_xor_sync(0xffffffffu, t, o);
    if ((c & 31) == 0) shm[c >> 5] = t;
    __syncthreads();
    if (c < 32) {
        float u = (c < 8) ? shm[c] : 0.0f;
        for (int o = 4; o; o >>= 1) u += __shfl_xor_sync(0xffffffffu, u, o);
        if (c == 0) shm[0] = u;
    }
    __syncthreads();
    float mean = shm[0] * (1.0f / DMODEL);
    __syncthreads();

    float d0 = x - mean;
    t = d0 * d0;
    for (int o = 16; o; o >>= 1) t += __shfl_xor_sync(0xffffffffu, t, o);
    if ((c & 31) == 0) shm[c >> 5] = t;
    __syncthreads();
    if (c < 32) {
        float u = (c < 8) ? shm[c] : 0.0f;
        for (int o = 4; o; o >>= 1) u += __shfl_xor_sync(0xffffffffu, u, o);
        if (c == 0) shm[0] = u;
    }
    __syncthreads();
    float var = shm[0] * (1.0f / DMODEL);
    tgt[idx] = d0 * rsqrtf(var + 1e-5f) * g[c] + b[c];
}

// ============================================================================
// Fused flash attention, fp32 inputs (self-attention; R7/R11-proven).
// 128 threads, 4 warps 2x2, warp tile 32x32.
// ============================================================================
#define FSMEM 91904
__global__ __launch_bounds__(128) void flash_attn(
    const float* __restrict__ Q, const float* __restrict__ K, const float* __restrict__ V,
    float* __restrict__ pO, float* __restrict__ pL,
    int ldq, int SP, int Schunk, int causal, float qscale)
{
    extern __shared__ char fsm[];
    bf16 (*Qh)[72] = (bf16(*)[72])(fsm);
    bf16 (*Ql)[72] = (bf16(*)[72])(fsm + 9216);
    bf16 (*Kh)[72] = (bf16(*)[72])(fsm + 18432);
    bf16 (*Kl)[72] = (bf16(*)[72])(fsm + 27648);
    bf16 (*Vh)[72] = (bf16(*)[72])(fsm + 36864);
    bf16 (*Vl)[72] = (bf16(*)[72])(fsm + 46080);
    float (*Ssm)[68] = (float(*)[68])(fsm + 55296);
    bf16 (*Ph)[72] = (bf16(*)[72])(fsm + 72704);
    bf16 (*Pl)[72] = (bf16(*)[72])(fsm + 81920);
    float* rs    = (float*)(fsm + 91136);
    float* rsum2 = (float*)(fsm + 91392);

    int sp = blockIdx.x, qt = blockIdx.y, n = blockIdx.z;
    int tid = threadIdx.x;
    int wid = tid >> 5;
    int wm = wid >> 1, wn = wid & 1;
    int pidx = (n*QT + qt)*SP + sp;
    int q0 = qt*64;
    int s0 = sp*Schunk;

    if (causal && s0 > q0 + 63) {
        for (int i = tid; i < 64*64; i += 128) pO[(size_t)pidx*4096 + i] = 0.f;
        if (tid < 64) pL[pidx*64 + tid] = 0.f;
        return;
    }

    const float* Qb = Q + (size_t)n*HD;
    const float* Kb = K + (size_t)n*HD;
    const float* Vb = V + (size_t)n*HD;

    #pragma unroll
    for (int it = 0; it < 8; it++) {
        int idx = it*128 + tid;
        int r = idx >> 4, c4 = (idx & 15)*4;
        float4 v = *(const float4*)&Qb[(size_t)(q0+r)*ldq + c4];
        split1(v.x, Qh[r][c4  ], Ql[r][c4  ]);
        split1(v.y, Qh[r][c4+1], Ql[r][c4+1]);
        split1(v.z, Qh[r][c4+2], Ql[r][c4+2]);
        split1(v.w, Qh[r][c4+3], Ql[r][c4+3]);
    }
    if (tid < 64) rs[tid] = 0.f;

    wmma::fragment<wmma::accumulator, 16,16,16, float> of[2][2];
    #pragma unroll
    for (int i=0;i<2;i++)
        #pragma unroll
        for (int j=0;j<2;j++) wmma::fill_fragment(of[i][j], 0.0f);

    int ntile = Schunk / 64;
    for (int t = 0; t < ntile; t++) {
        int sbase = s0 + t*64;
        if (causal && sbase > q0 + 63) break;
        __syncthreads();
        #pragma unroll
        for (int it = 0; it < 8; it++) {
            int idx = it*128 + tid;
            int r = idx >> 4, c4 = (idx & 15)*4;
            float4 kv = *(const float4*)&Kb[(size_t)(sbase+r)*ldq + c4];
            split1(kv.x, Kh[r][c4  ], Kl[r][c4  ]);
            split1(kv.y, Kh[r][c4+1], Kl[r][c4+1]);
            split1(kv.z, Kh[r][c4+2], Kl[r][c4+2]);
            split1(kv.w, Kh[r][c4+3], Kl[r][c4+3]);
            float4 vv = *(const float4*)&Vb[(size_t)(sbase+r)*ldq + c4];
            split1(vv.x, Vh[r][c4  ], Vl[r][c4  ]);
            split1(vv.y, Vh[r][c4+1], Vl[r][c4+1]);
            split1(vv.z, Vh[r][c4+2], Vl[r][c4+2]);
            split1(vv.w, Vh[r][c4+3], Vl[r][c4+3]);
        }
        __syncthreads();

        wmma::fragment<wmma::accumulator, 16,16,16, float> sf[2][2];
        #pragma unroll
        for (int i=0;i<2;i++)
            #pragma unroll
            for (int j=0;j<2;j++) wmma::fill_fragment(sf[i][j], 0.0f);
        #pragma unroll
        for (int kk = 0; kk < 4; kk++) {
            wmma::fragment<wmma::matrix_a, 16,16,16, bf16, wmma::row_major> ah[2], al[2];
            wmma::fragment<wmma::matrix_b, 16,16,16, bf16, wmma::col_major> bh[2], bl[2];
            #pragma unroll
            for (int i=0;i<2;i++) {
                wmma::load_matrix_sync(ah[i], &Qh[wm*32 + i*16][kk*16], 72);
                wmma::load_matrix_sync(al[i], &Ql[wm*32 + i*16][kk*16], 72);
            }
            #pragma unroll
            for (int j=0;j<2;j++) {
                wmma::load_matrix_sync(bh[j], &Kh[wn*32 + j*16][kk*16], 72);
                wmma::load_matrix_sync(bl[j], &Kl[wn*32 + j*16][kk*16], 72);
            }
            #pragma unroll
            for (int i=0;i<2;i++)
                #pragma unroll
                for (int j=0;j<2;j++) {
                    wmma::mma_sync(sf[i][j], ah[i], bh[j], sf[i][j]);
                    wmma::mma_sync(sf[i][j], ah[i], bl[j], sf[i][j]);
                    wmma::mma_sync(sf[i][j], al[i], bh[j], sf[i][j]);
                }
        }
        #pragma unroll
        for (int i=0;i<2;i++)
            #pragma unroll
            for (int j=0;j<2;j++)
                wmma::store_matrix_sync(&Ssm[wm*32+i*16][wn*32+j*16], sf[i][j], 68, wmma::mem_row_major);
        __syncthreads();

        {
            int r = tid >> 1, cbeg = (tid & 1) * 32;
            float psum = 0.f;
            #pragma unroll
            for (int c = 0; c < 32; c++) {
                int cc = cbeg + c;
                float x = Ssm[r][cc] * qscale;
                float e = (!causal || (sbase + cc) <= (q0 + r)) ? __expf(x) : 0.f;
                psum += e;
                split1(e, Ph[r][cc], Pl[r][cc]);
            }
            rsum2[tid] = psum;
        }
        __syncthreads();
        if (tid < 64) rs[tid] += rsum2[tid*2] + rsum2[tid*2+1];

        #pragma unroll
        for (int kk = 0; kk < 4; kk++) {
            wmma::fragment<wmma::matrix_a, 16,16,16, bf16, wmma::row_major> ah[2], al[2];
            wmma::fragment<wmma::matrix_b, 16,16,16, bf16, wmma::row_major> bh[2], bl[2];
            #pragma unroll
            for (int i=0;i<2;i++) {
                wmma::load_matrix_sync(ah[i], &Ph[wm*32 + i*16][kk*16], 72);
                wmma::load_matrix_sync(al[i], &Pl[wm*32 + i*16][kk*16], 72);
            }
            #pragma unroll
            for (int j=0;j<2;j++) {
                wmma::load_matrix_sync(bh[j], &Vh[kk*16][wn*32 + j*16], 72);
                wmma::load_matrix_sync(bl[j], &Vl[kk*16][wn*32 + j*16], 72);
            }
            #pragma unroll
            for (int i=0;i<2;i++)
                #pragma unroll
                for (int j=0;j<2;j++) {
                    wmma::mma_sync(of[i][j], ah[i], bh[j], of[i][j]);
                    wmma::mma_sync(of[i][j], ah[i], bl[j], of[i][j]);
                    wmma::mma_sync(of[i][j], al[i], bh[j], of[i][j]);
                }
        }
    }

    __syncthreads();
    #pragma unroll
    for (int i=0;i<2;i++)
        #pragma unroll
        for (int j=0;j<2;j++)
            wmma::store_matrix_sync(&Ssm[wm*32+i*16][wn*32+j*16], of[i][j], 68, wmma::mem_row_major);
    __syncthreads();

    float* po = pO + (size_t)pidx*4096;
    #pragma unroll
    for (int it = 0; it < 8; it++) {
        int idx = it*128 + tid;
        int r = idx >> 4, c4 = (idx & 15)*4;
        float4 v = make_float4(Ssm[r][c4], Ssm[r][c4+1], Ssm[r][c4+2], Ssm[r][c4+3]);
        *(float4*)&po[r*64 + c4] = v;
    }
    if (tid < 64) pL[pidx*64 + tid] = rs[tid];
}

// ============================================================================
// Fused flash attention, PRE-SPLIT bf16 K/V planes (cross-attention).
// K/V staging is pure float4 copies; Q (fp32) split once per CTA.
// ============================================================================
__global__ __launch_bounds__(128) void flash_attn_bf(
    const float* __restrict__ Q,
    const bf16* __restrict__ K, const bf16* __restrict__ V, size_t kvPlane,
    float* __restrict__ pO, float* __restrict__ pL,
    int ldq, int SP, int Schunk, float qscale)
{
    extern __shared__ char fsm[];
    bf16 (*Qh)[72] = (bf16(*)[72])(fsm);
    bf16 (*Ql)[72] = (bf16(*)[72])(fsm + 9216);
    bf16 (*Kh)[72] = (bf16(*)[72])(fsm + 18432);
    bf16 (*Kl)[72] = (bf16(*)[72])(fsm + 27648);
    bf16 (*Vh)[72] = (bf16(*)[72])(fsm + 36864);
    bf16 (*Vl)[72] = (bf16(*)[72])(fsm + 46080);
    float (*Ssm)[68] = (float(*)[68])(fsm + 55296);
    bf16 (*Ph)[72] = (bf16(*)[72])(fsm + 72704);
    bf16 (*Pl)[72] = (bf16(*)[72])(fsm + 81920);
    float* rs    = (float*)(fsm + 91136);
    float* rsum2 = (float*)(fsm + 91392);

    int sp = blockIdx.x, qt = blockIdx.y, n = blockIdx.z;
    int tid = threadIdx.x;
    int wid = tid >> 5;
    int wm = wid >> 1, wn = wid & 1;
    int pidx = (n*QT + qt)*SP + sp;
    int q0 = qt*64;
    int s0 = sp*Schunk;

    const float* Qb = Q + (size_t)n*HD;
    const bf16*  Kb = K + (size_t)n*HD;
    const bf16*  Vb = V + (size_t)n*HD;

    #pragma unroll
    for (int it = 0; it < 8; it++) {
        int idx = it*128 + tid;
        int r = idx >> 4, c4 = (idx & 15)*4;
        float4 v = *(const float4*)&Qb[(size_t)(q0+r)*ldq + c4];
        split1(v.x, Qh[r][c4  ], Ql[r][c4  ]);
        split1(v.y, Qh[r][c4+1], Ql[r][c4+1]);
        split1(v.z, Qh[r][c4+2], Ql[r][c4+2]);
        split1(v.w, Qh[r][c4+3], Ql[r][c4+3]);
    }
    if (tid < 64) rs[tid] = 0.f;

    wmma::fragment<wmma::accumulator, 16,16,16, float> of[2][2];
    #pragma unroll
    for (int i=0;i<2;i++)
        #pragma unroll
        for (int j=0;j<2;j++) wmma::fill_fragment(of[i][j], 0.0f);

    int ntile = Schunk / 64;
    for (int t = 0; t < ntile; t++) {
        int sbase = s0 + t*64;
        __syncthreads();
        // pure copy staging: 64 rows x 8 float4-slots (8 bf16 each) = 512 slots
        #pragma unroll
        for (int it = 0; it < 4; it++) {
            int idx = it*128 + tid;
            int r = idx >> 3, c8 = (idx & 7)*8;
            size_t ro = (size_t)(sbase+r)*ldq + c8;
            *(float4*)&Kh[r][c8] = *(const float4*)&Kb[ro];
            *(float4*)&Kl[r][c8] = *(const float4*)&Kb[kvPlane + ro];
            *(float4*)&Vh[r][c8] = *(const float4*)&Vb[ro];
            *(float4*)&Vl[r][c8] = *(const float4*)&Vb[kvPlane + ro];
        }
        __syncthreads();

        wmma::fragment<wmma::accumulator, 16,16,16, float> sf[2][2];
        #pragma unroll
        for (int i=0;i<2;i++)
            #pragma unroll
            for (int j=0;j<2;j++) wmma::fill_fragment(sf[i][j], 0.0f);
        #pragma unroll
        for (int kk = 0; kk < 4; kk++) {
            wmma::fragment<wmma::matrix_a, 16,16,16, bf16, wmma::row_major> ah[2], al[2];
            wmma::fragment<wmma::matrix_b, 16,16,16, bf16, wmma::col_major> bh[2], bl[2];
            #pragma unroll
            for (int i=0;i<2;i++) {
                wmma::load_matrix_sync(ah[i], &Qh[wm*32 + i*16][kk*16], 72);
                wmma::load_matrix_sync(al[i], &Ql[wm*32 + i*16][kk*16], 72);
            }
            #pragma unroll
            for (int j=0;j<2;j++) {
                wmma::load_matrix_sync(bh[j], &Kh[wn*32 + j*16][kk*16], 72);
                wmma::load_matrix_sync(bl[j], &Kl[wn*32 + j*16][kk*16], 72);
            }
            #pragma unroll
            for (int i=0;i<2;i++)
                #pragma unroll
                for (int j=0;j<2;j++) {
                    wmma::mma_sync(sf[i][j], ah[i], bh[j], sf[i][j]);
                    wmma::mma_sync(sf[i][j], ah[i], bl[j], sf[i][j]);
                    wmma::mma_sync(sf[i][j], al[i], bh[j], sf[i][j]);
                }
        }
        #pragma unroll
        for (int i=0;i<2;i++)
            #pragma unroll
            for (int j=0;j<2;j++)
                wmma::store_matrix_sync(&Ssm[wm*32+i*16][wn*32+j*16], sf[i][j], 68, wmma::mem_row_major);
        __syncthreads();

        {
            int r = tid >> 1, cbeg = (tid & 1) * 32;
            float psum = 0.f;
            #pragma unroll
            for (int c = 0; c < 32; c++) {
                int cc = cbeg + c;
                float e = __expf(Ssm[r][cc] * qscale);
                psum += e;
                split1(e, Ph[r][cc], Pl[r][cc]);
            }
            rsum2[tid] = psum;
        }
        __syncthreads();
        if (tid < 64) rs[tid] += rsum2[tid*2] + rsum2[tid*2+1];

        #pragma unroll
        for (int kk = 0; kk < 4; kk++) {
            wmma::fragment<wmma::matrix_a, 16,16,16, bf16, wmma::row_major> ah[2], al[2];
            wmma::fragment<wmma::matrix_b, 16,16,16, bf16, wmma::row_major> bh[2], bl[2];
            #pragma unroll
            for (int i=0;i<2;i++) {
                wmma::load_matrix_sync(ah[i], &Ph[wm*32 + i*16][kk*16], 72);
                wmma::load_matrix_sync(al[i], &Pl[wm*32 + i*16][kk*16], 72);
            }
            #pragma unroll
            for (int j=0;j<2;j++) {
                wmma::load_matrix_sync(bh[j], &Vh[kk*16][wn*32 + j*16], 72);
                wmma::load_matrix_sync(bl[j], &Vl[kk*16][wn*32 + j*16], 72);
            }
            #pragma unroll
            for (int i=0;i<2;i++)
                #pragma unroll
                for (int j=0;j<2;j++) {
                    wmma::mma_sync(of[i][j], ah[i], bh[j], of[i][j]);
                    wmma::mma_sync(of[i][j], ah[i], bl[j], of[i][j]);
                    wmma::mma_sync(of[i][j], al[i], bh[j], of[i][j]);
                }
        }
    }

    __syncthreads();
    #pragma unroll
    for (int i=0;i<2;i++)
        #pragma unroll
        for (int j=0;j<2;j++)
            wmma::store_matrix_sync(&Ssm[wm*32+i*16][wn*32+j*16], of[i][j], 68, wmma::mem_row_major);
    __syncthreads();

    float* po = pO + (size_t)pidx*4096;
    #pragma unroll
    for (int it = 0; it < 8; it++) {
        int idx = it*128 + tid;
        int r = idx >> 4, c4 = (idx & 15)*4;
        float4 v = make_float4(Ssm[r][c4], Ssm[r][c4+1], Ssm[r][c4+2], Ssm[r][c4+3]);
        *(float4*)&po[r*64 + c4] = v;
    }
    if (tid < 64) pL[pidx*64 + tid] = rs[tid];
}

// -------- combine flash partials: ao = sum_sp O_sp / sum_sp l_sp --------
__global__ void flash_combine(const float* __restrict__ pO, const float* __restrict__ pL,
                              float* __restrict__ ao, int ldq, int SP)
{
    int nq = blockIdx.x;
    int n = nq >> 2, qt = nq & 3;
    int q0 = qt*64;
    #pragma unroll
    for (int it = 0; it < 16; it++) {
        int idx = it*256 + threadIdx.x;
        int r = idx >> 6, c = idx & 63;
        float osum = 0.f, lsum = 0.f;
        for (int sp = 0; sp < SP; sp++) {
            int p = nq*SP + sp;
            osum += pO[(size_t)p*4096 + idx];
            lsum += pL[p*64 + r];
        }
        ao[(size_t)(q0+r)*ldq + n*HD + c] = osum / lsum;
    }
}

// -------- SIMT NT GEMM (vocab projection only) --------
__global__ __launch_bounds__(256) void gemm_nt(
    const float* __restrict__ A, int lda,
    const float* __restrict__ Bm, int ldb,
    const float* __restrict__ bias,
    float* __restrict__ C, int ldc,
    int M, int N, int K)
{
    __shared__ float As[16][68];
    __shared__ float Bs[16][68];
    int row0 = blockIdx.y * 64, col0 = blockIdx.x * 64;
    int tid = threadIdx.x;
    int tx = tid & 15, ty = tid >> 4;
    int lc = tid & 15, lr = tid >> 4;
    float acc[4][4] = {};
    for (int k0 = 0; k0 < K; k0 += 16) {
        #pragma unroll
        for (int it = 0; it < 4; it++)
            As[lc][lr + it*16] = A[(size_t)(row0 + lr + it*16) * lda + k0 + lc];
        #pragma unroll
        for (int it = 0; it < 4; it++) {
            int n = col0 + lr + it*16;
            Bs[lc][lr + it*16] = (n < N) ? Bm[(size_t)n * ldb + k0 + lc] : 0.0f;
        }
        __syncthreads();
        #pragma unroll
        for (int kk = 0; kk < 16; kk++) {
            float4 av = *(const float4*)&As[kk][ty*4];
            float4 bv = *(const float4*)&Bs[kk][tx*4];
            acc[0][0] += av.x*bv.x; acc[0][1] += av.x*bv.y; acc[0][2] += av.x*bv.z; acc[0][3] += av.x*bv.w;
            acc[1][0] += av.y*bv.x; acc[1][1] += av.y*bv.y; acc[1][2] += av.y*bv.z; acc[1][3] += av.y*bv.w;
            acc[2][0] += av.z*bv.x; acc[2][1] += av.z*bv.y; acc[2][2] += av.z*bv.z; acc[2][3] += av.z*bv.w;
            acc[3][0] += av.w*bv.x; acc[3][1] += av.w*bv.y; acc[3][2] += av.w*bv.z; acc[3][3] += av.w*bv.w;
        }
        __syncthreads();
    }
    #pragma unroll
    for (int i = 0; i < 4; i++) {
        int m = row0 + ty*4 + i;
        #pragma unroll
        for (int j = 0; j < 4; j++) {
            int n = col0 + tx*4 + j;
            if (n < N) C[(size_t)m*ldc + n] = acc[i][j] + bias[n];
        }
    }
}

extern "C" void kernel_launch(void* const* d_in, const int* in_sizes, int n_in,
                              void* d_out, int out_size) {
    const int*   tokens   = (const int*)  d_in[0];
    const float* features = (const float*)d_in[1];
    const float* emb      = (const float*)d_in[2];
    const float* sa_w     = (const float*)d_in[3];
    const float* sa_b     = (const float*)d_in[4];
    const float* ca_w     = (const float*)d_in[5];
    const float* ca_b     = (const float*)d_in[6];
    const float* ln_g     = (const float*)d_in[7];
    const float* ln_b     = (const float*)d_in[8];
    const float* ff_w1    = (const float*)d_in[9];
    const float* ff_b1    = (const float*)d_in[10];
    const float* ff_w2    = (const float*)d_in[11];
    const float* ff_b2    = (const float*)d_in[12];
    const float* out_w    = (const float*)d_in[13];
    const float* out_b    = (const float*)d_in[14];
    float* out = (float*)d_out;

    float *mem, *qkv, *tgt, *ao, *ffh, *part, *partl;
    bf16 *ckvb;
    cudaGetSymbolAddress((void**)&mem,  g_mem);
    cudaGetSymbolAddress((void**)&ckvb, g_ckvb);
    cudaGetSymbolAddress((void**)&qkv,  g_qkv);
    cudaGetSymbolAddress((void**)&tgt,  g_tgt);
    cudaGetSymbolAddress((void**)&ao,   g_ao);
    cudaGetSymbolAddress((void**)&ffh,  g_ffh);
    cudaGetSymbolAddress((void**)&part, g_part);
    cudaGetSymbolAddress((void**)&partl,g_partl);

    cudaFuncSetAttribute(flash_attn,    cudaFuncAttributeMaxDynamicSharedMemorySize, FSMEM);
    cudaFuncSetAttribute(flash_attn_bf, cudaFuncAttributeMaxDynamicSharedMemorySize, FSMEM);

    static cudaStream_t s2 = nullptr;
    static cudaEvent_t evRoot = nullptr;
    static cudaEvent_t evCkv[NLAYER];
    if (!s2) {
        cudaStreamCreateWithFlags(&s2, cudaStreamNonBlocking);
        cudaEventCreateWithFlags(&evRoot, cudaEventDisableTiming);
        for (int i = 0; i < NLAYER; i++)
            cudaEventCreateWithFlags(&evCkv[i], cudaEventDisableTiming);
    }

    float* q = qkv;
    float* k = qkv + (size_t)LB*DMODEL;
    float* v = qkv + (size_t)2*LB*DMODEL;

    const float qscale = 0.125f;
    const int DD = DMODEL*DMODEL;

    mem_kernel<<<(SBR*DMODEL)/256, 256>>>(features, mem);
    cudaEventRecord(evRoot, 0);

    // ckv projections on side stream -> bf16 hi/lo planes (no fp32 output)
    cudaStreamWaitEvent(s2, evRoot, 0);
    for (int i = 0; i < NLAYER; i++) {
        wgemm_nt<<<dim3(DMODEL/128, SBR/64, 2), 256, 0, s2>>>(
            mem, DMODEL,0,
            ca_w + (size_t)i*4*DD + DD, DMODEL, DD,
            ca_b + (size_t)i*4*DMODEL + DMODEL, DMODEL,
            (float*)0, ckvb + (size_t)i*CKV_L, CKVB_PL,
            DMODEL, SBR*DMODEL,
            SBR, DMODEL, DMODEL, 1, 1.0f, 0);
        cudaEventRecord(evCkv[i], s2);
    }

    embed_kernel<<<(LB*DMODEL)/256, 256>>>(tokens, emb, tgt);

    for (int i = 0; i < NLAYER; i++) {
        const float* W  = sa_w + (size_t)i*4*DD;
        const float* Bi = sa_b + (size_t)i*4*DMODEL;

        // ---- self-attention ----
        wgemm_nt<<<dim3(DMODEL/128, LB/64, 3*8), 256>>>(
            tgt, DMODEL,0, W, DMODEL,DD, (const float*)0,0,
            part, (bf16*)0,0, DMODEL, 0, LB, DMODEL, DMODEL, 8, 1.0f, 0);
        reduce_sk<<<(3*LB*DMODEL)/256, 256>>>(part, qkv, DMODEL, LB*DMODEL, LB, DMODEL, 8,
                                              Bi, DMODEL, 0);
        flash_attn<<<dim3(4, QT, BNH), 128, FSMEM>>>(q, k, v, part, partl,
                                                     LDQ, 4, 64, 1, qscale);
        flash_combine<<<BNH*QT, 256>>>(part, partl, ao, LDQ, 4);
        wgemm_nt<<<dim3(DMODEL/128, LB/64, 8), 256>>>(
            ao, DMODEL,0, W+3*DD, DMODEL,0, (const float*)0,0,
            part, (bf16*)0,0, DMODEL, 0, LB, DMODEL, DMODEL, 8, 1.0f, 0);
        reduce_ln<<<LB, DMODEL>>>(part, 8, Bi+3*DMODEL, tgt,
                                  ln_g + (size_t)(i*3+0)*DMODEL, ln_b + (size_t)(i*3+0)*DMODEL);

        // ---- cross-attention ----
        const float* Wc = ca_w + (size_t)i*4*DD;
        const float* Bc = ca_b + (size_t)i*4*DMODEL;
        bf16* ckp = ckvb + (size_t)i*CKV_L;
        bf16* cvp = ckp + (size_t)SBR*DMODEL;
        wgemm_nt<<<dim3(DMODEL/128, LB/64, 8), 256>>>(
            tgt, DMODEL,0, Wc, DMODEL,0, (const float*)0,0,
            part, (bf16*)0,0, DMODEL, 0, LB, DMODEL, DMODEL, 8, 1.0f, 0);
        reduce_sk<<<(LB*DMODEL)/256, 256>>>(part, q, DMODEL, 0, LB, DMODEL, 8,
                                            Bc, 0, 0);
        cudaStreamWaitEvent(0, evCkv[i], 0);
        flash_attn_bf<<<dim3(16, QT, BNH), 128, FSMEM>>>(q, ckp, cvp, CKVB_PL,
                                                         part, partl, LDQ, 16, 512, qscale);
        flash_combine<<<BNH*QT, 256>>>(part, partl, ao, LDQ, 16);
        wgemm_nt<<<dim3(DMODEL/128, LB/64, 8), 256>>>(
            ao, DMODEL,0, Wc+3*DD, DMODEL,0, (const float*)0,0,
            part, (bf16*)0,0, DMODEL, 0, LB, DMODEL, DMODEL, 8, 1.0f, 0);
        reduce_ln<<<LB, DMODEL>>>(part, 8, Bc+3*DMODEL, tgt,
                                  ln_g + (size_t)(i*3+1)*DMODEL, ln_b + (size_t)(i*3+1)*DMODEL);

        // ---- FFN ----
        wgemm_nt<<<dim3(DFF/128, LB/64, 1), 256>>>(
            tgt, DMODEL,0, ff_w1 + (size_t)i*DFF*DMODEL, DMODEL,0,
            ff_b1 + (size_t)i*DFF, 0,
            ffh, (bf16*)0,0, DFF, 0, LB, DFF, DMODEL, 1, 1.0f, 1);
        wgemm_nt<<<dim3(DMODEL/128, LB/64, 8), 256>>>(
            ffh, DFF,0, ff_w2 + (size_t)i*DMODEL*DFF, DFF,0, (const float*)0,0,
            part, (bf16*)0,0, DMODEL, 0, LB, DMODEL, DFF, 8, 1.0f, 0);
        reduce_ln<<<LB, DMODEL>>>(part, 8, ff_b2 + (size_t)i*DMODEL, tgt,
                                  ln_g + (size_t)(i*3+2)*DMODEL, ln_b + (size_t)(i*3+2)*DMODEL);
    }

    // final vocab projection -> d_out [L,B,V]
    gemm_nt<<<dim3((VOCAB+63)/64, LB/64), 256>>>(tgt, DMODEL, out_w, DMODEL, out_b,
                                                 out, VOCAB, LB, VOCAB, DMODEL);
}

// round 16
// speedup vs baseline: 1.0533x; 1.0533x over previous
#include <cuda_runtime.h>
#include <cuda_bf16.h>
#include <mma.h>

using namespace nvcuda;
typedef __nv_bfloat16 bf16;

// Problem constants
#define DMODEL 256
#define NHEAD  4
#define HD     64
#define NLAYER 8
#define DFF    1024
#define VOCAB  100
#define LT     256
#define BBATCH 2
#define FHH    32
#define FWW    256
#define SMEMN  (FHH*FWW)      // 8192
#define LB     (LT*BBATCH)    // 512
#define SBR    (SMEMN*BBATCH) // 16384
#define BNH    (BBATCH*NHEAD) // 8
#define LDQ    (BBATCH*DMODEL)// 512
#define QT     4              // q-tiles of 64 over LT

#define CKV_L   ((size_t)2*SBR*DMODEL)          // per-layer [ck|cv] elements
#define CKVB_PL ((size_t)NLAYER*CKV_L)          // plane offset (hi->lo)

#define LN10K 9.210340371976184f

// -------- scratch (device globals, allocation-free) --------
__device__ float g_mem[SBR*DMODEL];                    // 16 MB
__device__ __align__(16) bf16 g_ckvb[2*NLAYER*2*SBR*DMODEL];  // 268 MB bf16 hi/lo planes
__device__ float g_qkv[3*LB*DMODEL];
__device__ float g_tgt[LB*DMODEL];
__device__ float g_ao [LB*DMODEL];
__device__ float g_ffh[LB*DFF];
__device__ float g_part[4*1024*1024];                  // split-K / flash partials
__device__ float g_partl[BNH*QT*16*64];                // flash row-sum partials

__device__ __forceinline__ void split1(float v, bf16& h, bf16& l) {
    h = __float2bfloat16(v);
    l = __float2bfloat16(v - __bfloat162float(h));
}

// -------- memory tensor: features + 2D PE --------
__global__ void mem_kernel(const float* __restrict__ features, float* __restrict__ mem) {
    int idx = blockIdx.x * 256 + threadIdx.x;
    int c   = idx & (DMODEL-1);
    int row = idx >> 8;
    int b   = row & (BBATCH-1);
    int s   = row >> 1;
    int h   = s / FWW;
    int w   = s % FWW;
    float pe;
    if (c < DMODEL/2) {
        int e = c & ~1;
        float dv = __expf(-(float)e / (float)DMODEL * LN10K);
        float arg = (float)h * dv;
        pe = (c & 1) ? cosf(arg) : sinf(arg);
    } else {
        int e = (c - DMODEL/2) & ~1;
        float dv = __expf(-(float)e / (float)DMODEL * LN10K);
        float arg = (float)w * dv;
        pe = (c & 1) ? cosf(arg) : sinf(arg);
    }
    mem[idx] = features[(((size_t)b*DMODEL + c)*FHH + h)*FWW + w] + pe;
}

// -------- embedding + 1D PE --------
__global__ void embed_kernel(const int* __restrict__ tokens, const float* __restrict__ emb,
                             float* __restrict__ tgt) {
    int idx = blockIdx.x * 256 + threadIdx.x;
    int c   = idx & (DMODEL-1);
    int row = idx >> 8;
    int l   = row >> 1;
    int tok = tokens[row];
    int e = c & ~1;
    float dv = __expf(-(float)e / (float)DMODEL * LN10K);
    float arg = (float)l * dv;
    float pe = (c & 1) ? cosf(arg) : sinf(arg);
    tgt[idx] = emb[(size_t)tok*DMODEL + c] + pe;
}

// ============================================================================
// bf16x3 NT GEMM (R14-proven, BK=16, fp32-only epilogue — main chain).
// ============================================================================
__global__ __launch_bounds__(256) void wgemm_nt(
    const float* __restrict__ A, int lda, int aB,
    const float* __restrict__ Bm, int ldb, int bB,
    const float* __restrict__ bias, int biasB,
    float* __restrict__ C, int ldc, int cB,
    int M, int N, int K, int ksplit, float scale, int relu)
{
    __shared__ __align__(16) char smem_u[64*132*4];
    bf16 (*Ah)[24] = (bf16(*)[24])smem_u;
    bf16 (*Al)[24] = (bf16(*)[24])(smem_u + 3072);
    bf16 (*Bh)[24] = (bf16(*)[24])(smem_u + 6144);
    bf16 (*Bl)[24] = (bf16(*)[24])(smem_u + 12288);
    float (*Os)[132] = (float(*)[132])smem_u;

    int ks = blockIdx.z % ksplit, batch = blockIdx.z / ksplit;
    A  += (size_t)batch * aB;
    Bm += (size_t)batch * bB;
    if (ksplit > 1) {
        C += (size_t)blockIdx.z * M * N;
    } else {
        C += (size_t)batch * cB;
        if (bias) bias += (size_t)batch * biasB;
    }
    int row0 = blockIdx.y * 64, col0 = blockIdx.x * 128;
    int tid = threadIdx.x;
    int wid = tid >> 5;
    int wm = wid >> 2, wn = wid & 3;

    wmma::fragment<wmma::accumulator, 16,16,16, float> cf[2][2];
    #pragma unroll
    for (int i=0;i<2;i++)
        #pragma unroll
        for (int j=0;j<2;j++) wmma::fill_fragment(cf[i][j], 0.0f);

    int kbeg = ks * (K/ksplit), kend = kbeg + K/ksplit;
    int am = tid >> 2, ac = (tid & 3) * 4;

    for (int k0 = kbeg; k0 < kend; k0 += 16) {
        {
            float4 va = *(const float4*)&A[(size_t)(row0+am)*lda + k0 + ac];
            split1(va.x, Ah[am][ac  ], Al[am][ac  ]);
            split1(va.y, Ah[am][ac+1], Al[am][ac+1]);
            split1(va.z, Ah[am][ac+2], Al[am][ac+2]);
            split1(va.w, Ah[am][ac+3], Al[am][ac+3]);
            float4 v0 = *(const float4*)&Bm[(size_t)(col0+am)*ldb + k0 + ac];
            split1(v0.x, Bh[am][ac  ], Bl[am][ac  ]);
            split1(v0.y, Bh[am][ac+1], Bl[am][ac+1]);
            split1(v0.z, Bh[am][ac+2], Bl[am][ac+2]);
            split1(v0.w, Bh[am][ac+3], Bl[am][ac+3]);
            float4 v1 = *(const float4*)&Bm[(size_t)(col0+am+64)*ldb + k0 + ac];
            split1(v1.x, Bh[am+64][ac  ], Bl[am+64][ac  ]);
            split1(v1.y, Bh[am+64][ac+1], Bl[am+64][ac+1]);
            split1(v1.z, Bh[am+64][ac+2], Bl[am+64][ac+2]);
            split1(v1.w, Bh[am+64][ac+3], Bl[am+64][ac+3]);
        }
        __syncthreads();
        wmma::fragment<wmma::matrix_a, 16,16,16, bf16, wmma::row_major> ah[2], al[2];
        wmma::fragment<wmma::matrix_b, 16,16,16, bf16, wmma::col_major> bh[2], bl[2];
        #pragma unroll
        for (int i=0;i<2;i++) {
            wmma::load_matrix_sync(ah[i], &Ah[wm*32 + i*16][0], 24);
            wmma::load_matrix_sync(al[i], &Al[wm*32 + i*16][0], 24);
        }
        #pragma unroll
        for (int j=0;j<2;j++) {
            wmma::load_matrix_sync(bh[j], &Bh[wn*32 + j*16][0], 24);
            wmma::load_matrix_sync(bl[j], &Bl[wn*32 + j*16][0], 24);
        }
        #pragma unroll
        for (int i=0;i<2;i++)
            #pragma unroll
            for (int j=0;j<2;j++) {
                wmma::mma_sync(cf[i][j], ah[i], bh[j], cf[i][j]);
                wmma::mma_sync(cf[i][j], ah[i], bl[j], cf[i][j]);
                wmma::mma_sync(cf[i][j], al[i], bh[j], cf[i][j]);
            }
        __syncthreads();
    }

    #pragma unroll
    for (int i=0;i<2;i++)
        #pragma unroll
        for (int j=0;j<2;j++)
            wmma::store_matrix_sync(&Os[wm*32+i*16][wn*32+j*16], cf[i][j], 132, wmma::mem_row_major);
    __syncthreads();

    #pragma unroll
    for (int it = 0; it < 8; it++) {
        int idx = it*256 + tid;
        int m = idx >> 5;
        int c4 = (idx & 31) * 4;
        float4 v = *(float4*)&Os[m][c4];
        if (ksplit == 1) {
            if (bias) {
                v.x += bias[col0+c4];   v.y += bias[col0+c4+1];
                v.z += bias[col0+c4+2]; v.w += bias[col0+c4+3];
            }
            v.x *= scale; v.y *= scale; v.z *= scale; v.w *= scale;
            if (relu) {
                v.x = fmaxf(v.x, 0.f); v.y = fmaxf(v.y, 0.f);
                v.z = fmaxf(v.z, 0.f); v.w = fmaxf(v.w, 0.f);
            }
            *(float4*)&C[(size_t)(row0+m)*ldc + col0 + c4] = v;
        } else {
            *(float4*)&C[(size_t)(row0+m)*N + col0 + c4] = v;
        }
    }
}

// ============================================================================
// Side-stream-only clone: bf16 hi/lo plane output (ckv producer).
// Register bloat here is hidden (side stream has huge slack).
// ============================================================================
__global__ __launch_bounds__(256) void wgemm_nt_ckv(
    const float* __restrict__ A, int lda,
    const float* __restrict__ Bm, int ldb, int bB,
    const float* __restrict__ bias, int biasB,
    bf16* __restrict__ Cb, size_t cPlane, int ldc, int cB,
    int M, int N, int K)
{
    __shared__ __align__(16) char smem_u[64*132*4];
    bf16 (*Ah)[24] = (bf16(*)[24])smem_u;
    bf16 (*Al)[24] = (bf16(*)[24])(smem_u + 3072);
    bf16 (*Bh)[24] = (bf16(*)[24])(smem_u + 6144);
    bf16 (*Bl)[24] = (bf16(*)[24])(smem_u + 12288);
    float (*Os)[132] = (float(*)[132])smem_u;

    int batch = blockIdx.z;
    Bm   += (size_t)batch * bB;
    Cb   += (size_t)batch * cB;
    bias += (size_t)batch * biasB;
    int row0 = blockIdx.y * 64, col0 = blockIdx.x * 128;
    int tid = threadIdx.x;
    int wid = tid >> 5;
    int wm = wid >> 2, wn = wid & 3;

    wmma::fragment<wmma::accumulator, 16,16,16, float> cf[2][2];
    #pragma unroll
    for (int i=0;i<2;i++)
        #pragma unroll
        for (int j=0;j<2;j++) wmma::fill_fragment(cf[i][j], 0.0f);

    int am = tid >> 2, ac = (tid & 3) * 4;

    for (int k0 = 0; k0 < K; k0 += 16) {
        {
            float4 va = *(const float4*)&A[(size_t)(row0+am)*lda + k0 + ac];
            split1(va.x, Ah[am][ac  ], Al[am][ac  ]);
            split1(va.y, Ah[am][ac+1], Al[am][ac+1]);
            split1(va.z, Ah[am][ac+2], Al[am][ac+2]);
            split1(va.w, Ah[am][ac+3], Al[am][ac+3]);
            float4 v0 = *(const float4*)&Bm[(size_t)(col0+am)*ldb + k0 + ac];
            split1(v0.x, Bh[am][ac  ], Bl[am][ac  ]);
            split1(v0.y, Bh[am][ac+1], Bl[am][ac+1]);
            split1(v0.z, Bh[am][ac+2], Bl[am][ac+2]);
            split1(v0.w, Bh[am][ac+3], Bl[am][ac+3]);
            float4 v1 = *(const float4*)&Bm[(size_t)(col0+am+64)*ldb + k0 + ac];
            split1(v1.x, Bh[am+64][ac  ], Bl[am+64][ac  ]);
            split1(v1.y, Bh[am+64][ac+1], Bl[am+64][ac+1]);
            split1(v1.z, Bh[am+64][ac+2], Bl[am+64][ac+2]);
            split1(v1.w, Bh[am+64][ac+3], Bl[am+64][ac+3]);
        }
        __syncthreads();
        wmma::fragment<wmma::matrix_a, 16,16,16, bf16, wmma::row_major> ah[2], al[2];
        wmma::fragment<wmma::matrix_b, 16,16,16, bf16, wmma::col_major> bh[2], bl[2];
        #pragma unroll
        for (int i=0;i<2;i++) {
            wmma::load_matrix_sync(ah[i], &Ah[wm*32 + i*16][0], 24);
            wmma::load_matrix_sync(al[i], &Al[wm*32 + i*16][0], 24);
        }
        #pragma unroll
        for (int j=0;j<2;j++) {
            wmma::load_matrix_sync(bh[j], &Bh[wn*32 + j*16][0], 24);
            wmma::load_matrix_sync(bl[j], &Bl[wn*32 + j*16][0], 24);
        }
        #pragma unroll
        for (int i=0;i<2;i++)
            #pragma unroll
            for (int j=0;j<2;j++) {
                wmma::mma_sync(cf[i][j], ah[i], bh[j], cf[i][j]);
                wmma::mma_sync(cf[i][j], ah[i], bl[j], cf[i][j]);
                wmma::mma_sync(cf[i][j], al[i], bh[j], cf[i][j]);
            }
        __syncthreads();
    }

    #pragma unroll
    for (int i=0;i<2;i++)
        #pragma unroll
        for (int j=0;j<2;j++)
            wmma::store_matrix_sync(&Os[wm*32+i*16][wn*32+j*16], cf[i][j], 132, wmma::mem_row_major);
    __syncthreads();

    #pragma unroll
    for (int it = 0; it < 8; it++) {
        int idx = it*256 + tid;
        int m = idx >> 5;
        int c4 = (idx & 31) * 4;
        float4 v = *(float4*)&Os[m][c4];
        v.x += bias[col0+c4];   v.y += bias[col0+c4+1];
        v.z += bias[col0+c4+2]; v.w += bias[col0+c4+3];
        size_t o = (size_t)(row0+m)*ldc + col0 + c4;
        bf16 hv[4], lv[4];
        split1(v.x, hv[0], lv[0]); split1(v.y, hv[1], lv[1]);
        split1(v.z, hv[2], lv[2]); split1(v.w, hv[3], lv[3]);
        *(uint2*)&Cb[o] = *(uint2*)hv;
        *(uint2*)&Cb[cPlane + o] = *(uint2*)lv;
    }
}

// -------- split-K reduce (plain fp32 out) --------
__global__ void reduce_sk(const float* __restrict__ P, float* __restrict__ C,
                          int ldc, int cB, int M, int N, int ksplit,
                          const float* __restrict__ bias, int biasB, int relu)
{
    int idx = blockIdx.x * 256 + threadIdx.x;
    int n = idx % N;
    int mb = idx / N;
    int m = mb % M;
    int batch = mb / M;
    const float* p = P + ((size_t)batch*ksplit)*M*N + (size_t)m*N + n;
    float s = 0.0f;
    for (int ksi = 0; ksi < ksplit; ksi++) s += p[(size_t)ksi*M*N];
    if (bias) s += bias[(size_t)batch*biasB + n];
    if (relu) s = fmaxf(s, 0.0f);
    C[(size_t)batch*cB + (size_t)m*ldc + n] = s;
}

// -------- FUSED: split-K reduce + bias + residual + LayerNorm (in-place tgt) ----
__global__ void reduce_ln(const float* __restrict__ P, int ksplit,
                          const float* __restrict__ bias,
                          float* __restrict__ tgt,
                          const float* __restrict__ g, const float* __restrict__ b)
{
    __shared__ float shm[8];
    int row = blockIdx.x, c = threadIdx.x;
    size_t idx = (size_t)row * DMODEL + c;
    float s = 0.0f;
    for (int ksi = 0; ksi < ksplit; ksi++) s += P[(size_t)ksi*LB*DMODEL + idx];
    s += bias[c];
    float x = tgt[idx] + s;

    float t = x;
    for (int o = 16; o; o >>= 1) t += __shfl_xor_sync(0xffffffffu, t, o);
    if ((c & 31) == 0) shm[c >> 5] = t;
    __syncthreads();
    if (c < 32) {
        float u = (c < 8) ? shm[c] : 0.0f;
        for (int o = 4; o; o >>= 1) u += __shfl_xor_sync(0xffffffffu, u, o);
        if (c == 0) shm[0] = u;
    }
    __syncthreads();
    float mean = shm[0] * (1.0f / DMODEL);
    __syncthreads();

    float d0 = x - mean;
    t = d0 * d0;
    for (int o = 16; o; o >>= 1) t += __shfl_xor_sync(0xffffffffu, t, o);
    if ((c & 31) == 0) shm[c >> 5] = t;
    __syncthreads();
    if (c < 32) {
        float u = (c < 8) ? shm[c] : 0.0f;
        for (int o = 4; o; o >>= 1) u += __shfl_xor_sync(0xffffffffu, u, o);
        if (c == 0) shm[0] = u;
    }
    __syncthreads();
    float var = shm[0] * (1.0f / DMODEL);
    tgt[idx] = d0 * rsqrtf(var + 1e-5f) * g[c] + b[c];
}

// ============================================================================
// Fused flash attention, fp32 inputs (self-attention; R7/R11-proven).
// ============================================================================
#define FSMEM 91904
__global__ __launch_bounds__(128) void flash_attn(
    const float* __restrict__ Q, const float* __restrict__ K, const float* __restrict__ V,
    float* __restrict__ pO, float* __restrict__ pL,
    int ldq, int SP, int Schunk, int causal, float qscale)
{
    extern __shared__ char fsm[];
    bf16 (*Qh)[72] = (bf16(*)[72])(fsm);
    bf16 (*Ql)[72] = (bf16(*)[72])(fsm + 9216);
    bf16 (*Kh)[72] = (bf16(*)[72])(fsm + 18432);
    bf16 (*Kl)[72] = (bf16(*)[72])(fsm + 27648);
    bf16 (*Vh)[72] = (bf16(*)[72])(fsm + 36864);
    bf16 (*Vl)[72] = (bf16(*)[72])(fsm + 46080);
    float (*Ssm)[68] = (float(*)[68])(fsm + 55296);
    bf16 (*Ph)[72] = (bf16(*)[72])(fsm + 72704);
    bf16 (*Pl)[72] = (bf16(*)[72])(fsm + 81920);
    float* rs    = (float*)(fsm + 91136);
    float* rsum2 = (float*)(fsm + 91392);

    int sp = blockIdx.x, qt = blockIdx.y, n = blockIdx.z;
    int tid = threadIdx.x;
    int wid = tid >> 5;
    int wm = wid >> 1, wn = wid & 1;
    int pidx = (n*QT + qt)*SP + sp;
    int q0 = qt*64;
    int s0 = sp*Schunk;

    if (causal && s0 > q0 + 63) {
        for (int i = tid; i < 64*64; i += 128) pO[(size_t)pidx*4096 + i] = 0.f;
        if (tid < 64) pL[pidx*64 + tid] = 0.f;
        return;
    }

    const float* Qb = Q + (size_t)n*HD;
    const float* Kb = K + (size_t)n*HD;
    const float* Vb = V + (size_t)n*HD;

    #pragma unroll
    for (int it = 0; it < 8; it++) {
        int idx = it*128 + tid;
        int r = idx >> 4, c4 = (idx & 15)*4;
        float4 v = *(const float4*)&Qb[(size_t)(q0+r)*ldq + c4];
        split1(v.x, Qh[r][c4  ], Ql[r][c4  ]);
        split1(v.y, Qh[r][c4+1], Ql[r][c4+1]);
        split1(v.z, Qh[r][c4+2], Ql[r][c4+2]);
        split1(v.w, Qh[r][c4+3], Ql[r][c4+3]);
    }
    if (tid < 64) rs[tid] = 0.f;

    wmma::fragment<wmma::accumulator, 16,16,16, float> of[2][2];
    #pragma unroll
    for (int i=0;i<2;i++)
        #pragma unroll
        for (int j=0;j<2;j++) wmma::fill_fragment(of[i][j], 0.0f);

    int ntile = Schunk / 64;
    for (int t = 0; t < ntile; t++) {
        int sbase = s0 + t*64;
        if (causal && sbase > q0 + 63) break;
        __syncthreads();
        #pragma unroll
        for (int it = 0; it < 8; it++) {
            int idx = it*128 + tid;
            int r = idx >> 4, c4 = (idx & 15)*4;
            float4 kv = *(const float4*)&Kb[(size_t)(sbase+r)*ldq + c4];
            split1(kv.x, Kh[r][c4  ], Kl[r][c4  ]);
            split1(kv.y, Kh[r][c4+1], Kl[r][c4+1]);
            split1(kv.z, Kh[r][c4+2], Kl[r][c4+2]);
            split1(kv.w, Kh[r][c4+3], Kl[r][c4+3]);
            float4 vv = *(const float4*)&Vb[(size_t)(sbase+r)*ldq + c4];
            split1(vv.x, Vh[r][c4  ], Vl[r][c4  ]);
            split1(vv.y, Vh[r][c4+1], Vl[r][c4+1]);
            split1(vv.z, Vh[r][c4+2], Vl[r][c4+2]);
            split1(vv.w, Vh[r][c4+3], Vl[r][c4+3]);
        }
        __syncthreads();

        wmma::fragment<wmma::accumulator, 16,16,16, float> sf[2][2];
        #pragma unroll
        for (int i=0;i<2;i++)
            #pragma unroll
            for (int j=0;j<2;j++) wmma::fill_fragment(sf[i][j], 0.0f);
        #pragma unroll
        for (int kk = 0; kk < 4; kk++) {
            wmma::fragment<wmma::matrix_a, 16,16,16, bf16, wmma::row_major> ah[2], al[2];
            wmma::fragment<wmma::matrix_b, 16,16,16, bf16, wmma::col_major> bh[2], bl[2];
            #pragma unroll
            for (int i=0;i<2;i++) {
                wmma::load_matrix_sync(ah[i], &Qh[wm*32 + i*16][kk*16], 72);
                wmma::load_matrix_sync(al[i], &Ql[wm*32 + i*16][kk*16], 72);
            }
            #pragma unroll
            for (int j=0;j<2;j++) {
                wmma::load_matrix_sync(bh[j], &Kh[wn*32 + j*16][kk*16], 72);
                wmma::load_matrix_sync(bl[j], &Kl[wn*32 + j*16][kk*16], 72);
            }
            #pragma unroll
            for (int i=0;i<2;i++)
                #pragma unroll
                for (int j=0;j<2;j++) {
                    wmma::mma_sync(sf[i][j], ah[i], bh[j], sf[i][j]);
                    wmma::mma_sync(sf[i][j], ah[i], bl[j], sf[i][j]);
                    wmma::mma_sync(sf[i][j], al[i], bh[j], sf[i][j]);
                }
        }
        #pragma unroll
        for (int i=0;i<2;i++)
            #pragma unroll
            for (int j=0;j<2;j++)
                wmma::store_matrix_sync(&Ssm[wm*32+i*16][wn*32+j*16], sf[i][j], 68, wmma::mem_row_major);
        __syncthreads();

        {
            int r = tid >> 1, cbeg = (tid & 1) * 32;
            float psum = 0.f;
            #pragma unroll
            for (int c = 0; c < 32; c++) {
                int cc = cbeg + c;
                float x = Ssm[r][cc] * qscale;
                float e = (!causal || (sbase + cc) <= (q0 + r)) ? __expf(x) : 0.f;
                psum += e;
                split1(e, Ph[r][cc], Pl[r][cc]);
            }
            rsum2[tid] = psum;
        }
        __syncthreads();
        if (tid < 64) rs[tid] += rsum2[tid*2] + rsum2[tid*2+1];

        #pragma unroll
        for (int kk = 0; kk < 4; kk++) {
            wmma::fragment<wmma::matrix_a, 16,16,16, bf16, wmma::row_major> ah[2], al[2];
            wmma::fragment<wmma::matrix_b, 16,16,16, bf16, wmma::row_major> bh[2], bl[2];
            #pragma unroll
            for (int i=0;i<2;i++) {
                wmma::load_matrix_sync(ah[i], &Ph[wm*32 + i*16][kk*16], 72);
                wmma::load_matrix_sync(al[i], &Pl[wm*32 + i*16][kk*16], 72);
            }
            #pragma unroll
            for (int j=0;j<2;j++) {
                wmma::load_matrix_sync(bh[j], &Vh[kk*16][wn*32 + j*16], 72);
                wmma::load_matrix_sync(bl[j], &Vl[kk*16][wn*32 + j*16], 72);
            }
            #pragma unroll
            for (int i=0;i<2;i++)
                #pragma unroll
                for (int j=0;j<2;j++) {
                    wmma::mma_sync(of[i][j], ah[i], bh[j], of[i][j]);
                    wmma::mma_sync(of[i][j], ah[i], bl[j], of[i][j]);
                    wmma::mma_sync(of[i][j], al[i], bh[j], of[i][j]);
                }
        }
    }

    __syncthreads();
    #pragma unroll
    for (int i=0;i<2;i++)
        #pragma unroll
        for (int j=0;j<2;j++)
            wmma::store_matrix_sync(&Ssm[wm*32+i*16][wn*32+j*16], of[i][j], 68, wmma::mem_row_major);
    __syncthreads();

    float* po = pO + (size_t)pidx*4096;
    #pragma unroll
    for (int it = 0; it < 8; it++) {
        int idx = it*128 + tid;
        int r = idx >> 4, c4 = (idx & 15)*4;
        float4 v = make_float4(Ssm[r][c4], Ssm[r][c4+1], Ssm[r][c4+2], Ssm[r][c4+3]);
        *(float4*)&po[r*64 + c4] = v;
    }
    if (tid < 64) pL[pidx*64 + tid] = rs[tid];
}

// ============================================================================
// Fused flash attention, PRE-SPLIT bf16 K/V planes (cross-attention).
// K/V staging is pure float4 copies; Q (fp32) split once per CTA.
// ============================================================================
__global__ __launch_bounds__(128) void flash_attn_bf(
    const float* __restrict__ Q,
    const bf16* __restrict__ K, const bf16* __restrict__ V, size_t kvPlane,
    float* __restrict__ pO, float* __restrict__ pL,
    int ldq, int SP, int Schunk, float qscale)
{
    extern __shared__ char fsm[];
    bf16 (*Qh)[72] = (bf16(*)[72])(fsm);
    bf16 (*Ql)[72] = (bf16(*)[72])(fsm + 9216);
    bf16 (*Kh)[72] = (bf16(*)[72])(fsm + 18432);
    bf16 (*Kl)[72] = (bf16(*)[72])(fsm + 27648);
    bf16 (*Vh)[72] = (bf16(*)[72])(fsm + 36864);
    bf16 (*Vl)[72] = (bf16(*)[72])(fsm + 46080);
    float (*Ssm)[68] = (float(*)[68])(fsm + 55296);
    bf16 (*Ph)[72] = (bf16(*)[72])(fsm + 72704);
    bf16 (*Pl)[72] = (bf16(*)[72])(fsm + 81920);
    float* rs    = (float*)(fsm + 91136);
    float* rsum2 = (float*)(fsm + 91392);

    int sp = blockIdx.x, qt = blockIdx.y, n = blockIdx.z;
    int tid = threadIdx.x;
    int wid = tid >> 5;
    int wm = wid >> 1, wn = wid & 1;
    int pidx = (n*QT + qt)*SP + sp;
    int q0 = qt*64;
    int s0 = sp*Schunk;

    const float* Qb = Q + (size_t)n*HD;
    const bf16*  Kb = K + (size_t)n*HD;
    const bf16*  Vb = V + (size_t)n*HD;

    #pragma unroll
    for (int it = 0; it < 8; it++) {
        int idx = it*128 + tid;
        int r = idx >> 4, c4 = (idx & 15)*4;
        float4 v = *(const float4*)&Qb[(size_t)(q0+r)*ldq + c4];
        split1(v.x, Qh[r][c4  ], Ql[r][c4  ]);
        split1(v.y, Qh[r][c4+1], Ql[r][c4+1]);
        split1(v.z, Qh[r][c4+2], Ql[r][c4+2]);
        split1(v.w, Qh[r][c4+3], Ql[r][c4+3]);
    }
    if (tid < 64) rs[tid] = 0.f;

    wmma::fragment<wmma::accumulator, 16,16,16, float> of[2][2];
    #pragma unroll
    for (int i=0;i<2;i++)
        #pragma unroll
        for (int j=0;j<2;j++) wmma::fill_fragment(of[i][j], 0.0f);

    int ntile = Schunk / 64;
    for (int t = 0; t < ntile; t++) {
        int sbase = s0 + t*64;
        __syncthreads();
        // pure copy staging: 64 rows x 8 float4-slots (8 bf16 each)
        #pragma unroll
        for (int it = 0; it < 4; it++) {
            int idx = it*128 + tid;
            int r = idx >> 3, c8 = (idx & 7)*8;
            size_t ro = (size_t)(sbase+r)*ldq + c8;
            *(float4*)&Kh[r][c8] = *(const float4*)&Kb[ro];
            *(float4*)&Kl[r][c8] = *(const float4*)&Kb[kvPlane + ro];
            *(float4*)&Vh[r][c8] = *(const float4*)&Vb[ro];
            *(float4*)&Vl[r][c8] = *(const float4*)&Vb[kvPlane + ro];
        }
        __syncthreads();

        wmma::fragment<wmma::accumulator, 16,16,16, float> sf[2][2];
        #pragma unroll
        for (int i=0;i<2;i++)
            #pragma unroll
            for (int j=0;j<2;j++) wmma::fill_fragment(sf[i][j], 0.0f);
        #pragma unroll
        for (int kk = 0; kk < 4; kk++) {
            wmma::fragment<wmma::matrix_a, 16,16,16, bf16, wmma::row_major> ah[2], al[2];
            wmma::fragment<wmma::matrix_b, 16,16,16, bf16, wmma::col_major> bh[2], bl[2];
            #pragma unroll
            for (int i=0;i<2;i++) {
                wmma::load_matrix_sync(ah[i], &Qh[wm*32 + i*16][kk*16], 72);
                wmma::load_matrix_sync(al[i], &Ql[wm*32 + i*16][kk*16], 72);
            }
            #pragma unroll
            for (int j=0;j<2;j++) {
                wmma::load_matrix_sync(bh[j], &Kh[wn*32 + j*16][kk*16], 72);
                wmma::load_matrix_sync(bl[j], &Kl[wn*32 + j*16][kk*16], 72);
            }
            #pragma unroll
            for (int i=0;i<2;i++)
                #pragma unroll
                for (int j=0;j<2;j++) {
                    wmma::mma_sync(sf[i][j], ah[i], bh[j], sf[i][j]);
                    wmma::mma_sync(sf[i][j], ah[i], bl[j], sf[i][j]);
                    wmma::mma_sync(sf[i][j], al[i], bh[j], sf[i][j]);
                }
        }
        #pragma unroll
        for (int i=0;i<2;i++)
            #pragma unroll
            for (int j=0;j<2;j++)
                wmma::store_matrix_sync(&Ssm[wm*32+i*16][wn*32+j*16], sf[i][j], 68, wmma::mem_row_major);
        __syncthreads();

        {
            int r = tid >> 1, cbeg = (tid & 1) * 32;
            float psum = 0.f;
            #pragma unroll
            for (int c = 0; c < 32; c++) {
                int cc = cbeg + c;
                float e = __expf(Ssm[r][cc] * qscale);
                psum += e;
                split1(e, Ph[r][cc], Pl[r][cc]);
            }
            rsum2[tid] = psum;
        }
        __syncthreads();
        if (tid < 64) rs[tid] += rsum2[tid*2] + rsum2[tid*2+1];

        #pragma unroll
        for (int kk = 0; kk < 4; kk++) {
            wmma::fragment<wmma::matrix_a, 16,16,16, bf16, wmma::row_major> ah[2], al[2];
            wmma::fragment<wmma::matrix_b, 16,16,16, bf16, wmma::row_major> bh[2], bl[2];
            #pragma unroll
            for (int i=0;i<2;i++) {
                wmma::load_matrix_sync(ah[i], &Ph[wm*32 + i*16][kk*16], 72);
                wmma::load_matrix_sync(al[i], &Pl[wm*32 + i*16][kk*16], 72);
            }
            #pragma unroll
            for (int j=0;j<2;j++) {
                wmma::load_matrix_sync(bh[j], &Vh[kk*16][wn*32 + j*16], 72);
                wmma::load_matrix_sync(bl[j], &Vl[kk*16][wn*32 + j*16], 72);
            }
            #pragma unroll
            for (int i=0;i<2;i++)
                #pragma unroll
                for (int j=0;j<2;j++) {
                    wmma::mma_sync(of[i][j], ah[i], bh[j], of[i][j]);
                    wmma::mma_sync(of[i][j], ah[i], bl[j], of[i][j]);
                    wmma::mma_sync(of[i][j], al[i], bh[j], of[i][j]);
                }
        }
    }

    __syncthreads();
    #pragma unroll
    for (int i=0;i<2;i++)
        #pragma unroll
        for (int j=0;j<2;j++)
            wmma::store_matrix_sync(&Ssm[wm*32+i*16][wn*32+j*16], of[i][j], 68, wmma::mem_row_major);
    __syncthreads();

    float* po = pO + (size_t)pidx*4096;
    #pragma unroll
    for (int it = 0; it < 8; it++) {
        int idx = it*128 + tid;
        int r = idx >> 4, c4 = (idx & 15)*4;
        float4 v = make_float4(Ssm[r][c4], Ssm[r][c4+1], Ssm[r][c4+2], Ssm[r][c4+3]);
        *(float4*)&po[r*64 + c4] = v;
    }
    if (tid < 64) pL[pidx*64 + tid] = rs[tid];
}

// -------- combine flash partials: ao = sum_sp O_sp / sum_sp l_sp --------
__global__ void flash_combine(const float* __restrict__ pO, const float* __restrict__ pL,
                              float* __restrict__ ao, int ldq, int SP)
{
    int nq = blockIdx.x;
    int n = nq >> 2, qt = nq & 3;
    int q0 = qt*64;
    #pragma unroll
    for (int it = 0; it < 16; it++) {
        int idx = it*256 + threadIdx.x;
        int r = idx >> 6, c = idx & 63;
        float osum = 0.f, lsum = 0.f;
        for (int sp = 0; sp < SP; sp++) {
            int p = nq*SP + sp;
            osum += pO[(size_t)p*4096 + idx];
            lsum += pL[p*64 + r];
        }
        ao[(size_t)(q0+r)*ldq + n*HD + c] = osum / lsum;
    }
}

// -------- SIMT NT GEMM (vocab projection only) --------
__global__ __launch_bounds__(256) void gemm_nt(
    const float* __restrict__ A, int lda,
    const float* __restrict__ Bm, int ldb,
    const float* __restrict__ bias,
    float* __restrict__ C, int ldc,
    int M, int N, int K)
{
    __shared__ float As[16][68];
    __shared__ float Bs[16][68];
    int row0 = blockIdx.y * 64, col0 = blockIdx.x * 64;
    int tid = threadIdx.x;
    int tx = tid & 15, ty = tid >> 4;
    int lc = tid & 15, lr = tid >> 4;
    float acc[4][4] = {};
    for (int k0 = 0; k0 < K; k0 += 16) {
        #pragma unroll
        for (int it = 0; it < 4; it++)
            As[lc][lr + it*16] = A[(size_t)(row0 + lr + it*16) * lda + k0 + lc];
        #pragma unroll
        for (int it = 0; it < 4; it++) {
            int n = col0 + lr + it*16;
            Bs[lc][lr + it*16] = (n < N) ? Bm[(size_t)n * ldb + k0 + lc] : 0.0f;
        }
        __syncthreads();
        #pragma unroll
        for (int kk = 0; kk < 16; kk++) {
            float4 av = *(const float4*)&As[kk][ty*4];
            float4 bv = *(const float4*)&Bs[kk][tx*4];
            acc[0][0] += av.x*bv.x; acc[0][1] += av.x*bv.y; acc[0][2] += av.x*bv.z; acc[0][3] += av.x*bv.w;
            acc[1][0] += av.y*bv.x; acc[1][1] += av.y*bv.y; acc[1][2] += av.y*bv.z; acc[1][3] += av.y*bv.w;
            acc[2][0] += av.z*bv.x; acc[2][1] += av.z*bv.y; acc[2][2] += av.z*bv.z; acc[2][3] += av.z*bv.w;
            acc[3][0] += av.w*bv.x; acc[3][1] += av.w*bv.y; acc[3][2] += av.w*bv.z; acc[3][3] += av.w*bv.w;
        }
        __syncthreads();
    }
    #pragma unroll
    for (int i = 0; i < 4; i++) {
        int m = row0 + ty*4 + i;
        #pragma unroll
        for (int j = 0; j < 4; j++) {
            int n = col0 + tx*4 + j;
            if (n < N) C[(size_t)m*ldc + n] = acc[i][j] + bias[n];
        }
    }
}

extern "C" void kernel_launch(void* const* d_in, const int* in_sizes, int n_in,
                              void* d_out, int out_size) {
    const int*   tokens   = (const int*)  d_in[0];
    const float* features = (const float*)d_in[1];
    const float* emb      = (const float*)d_in[2];
    const float* sa_w     = (const float*)d_in[3];
    const float* sa_b     = (const float*)d_in[4];
    const float* ca_w     = (const float*)d_in[5];
    const float* ca_b     = (const float*)d_in[6];
    const float* ln_g     = (const float*)d_in[7];
    const float* ln_b     = (const float*)d_in[8];
    const float* ff_w1    = (const float*)d_in[9];
    const float* ff_b1    = (const float*)d_in[10];
    const float* ff_w2    = (const float*)d_in[11];
    const float* ff_b2    = (const float*)d_in[12];
    const float* out_w    = (const float*)d_in[13];
    const float* out_b    = (const float*)d_in[14];
    float* out = (float*)d_out;

    float *mem, *qkv, *tgt, *ao, *ffh, *part, *partl;
    bf16 *ckvb;
    cudaGetSymbolAddress((void**)&mem,  g_mem);
    cudaGetSymbolAddress((void**)&ckvb, g_ckvb);
    cudaGetSymbolAddress((void**)&qkv,  g_qkv);
    cudaGetSymbolAddress((void**)&tgt,  g_tgt);
    cudaGetSymbolAddress((void**)&ao,   g_ao);
    cudaGetSymbolAddress((void**)&ffh,  g_ffh);
    cudaGetSymbolAddress((void**)&part, g_part);
    cudaGetSymbolAddress((void**)&partl,g_partl);

    cudaFuncSetAttribute(flash_attn,    cudaFuncAttributeMaxDynamicSharedMemorySize, FSMEM);
    cudaFuncSetAttribute(flash_attn_bf, cudaFuncAttributeMaxDynamicSharedMemorySize, FSMEM);

    static cudaStream_t s2 = nullptr;
    static cudaEvent_t evRoot = nullptr;
    static cudaEvent_t evCkv[NLAYER];
    if (!s2) {
        cudaStreamCreateWithFlags(&s2, cudaStreamNonBlocking);
        cudaEventCreateWithFlags(&evRoot, cudaEventDisableTiming);
        for (int i = 0; i < NLAYER; i++)
            cudaEventCreateWithFlags(&evCkv[i], cudaEventDisableTiming);
    }

    float* q = qkv;
    float* k = qkv + (size_t)LB*DMODEL;
    float* v = qkv + (size_t)2*LB*DMODEL;

    const float qscale = 0.125f;
    const int DD = DMODEL*DMODEL;

    mem_kernel<<<(SBR*DMODEL)/256, 256>>>(features, mem);
    cudaEventRecord(evRoot, 0);

    // ckv projections on side stream -> bf16 hi/lo planes (dedicated kernel)
    cudaStreamWaitEvent(s2, evRoot, 0);
    for (int i = 0; i < NLAYER; i++) {
        wgemm_nt_ckv<<<dim3(DMODEL/128, SBR/64, 2), 256, 0, s2>>>(
            mem, DMODEL,
            ca_w + (size_t)i*4*DD + DD, DMODEL, DD,
            ca_b + (size_t)i*4*DMODEL + DMODEL, DMODEL,
            ckvb + (size_t)i*CKV_L, CKVB_PL, DMODEL, SBR*DMODEL,
            SBR, DMODEL, DMODEL);
        cudaEventRecord(evCkv[i], s2);
    }

    embed_kernel<<<(LB*DMODEL)/256, 256>>>(tokens, emb, tgt);

    for (int i = 0; i < NLAYER; i++) {
        const float* W  = sa_w + (size_t)i*4*DD;
        const float* Bi = sa_b + (size_t)i*4*DMODEL;

        // ---- self-attention ----
        wgemm_nt<<<dim3(DMODEL/128, LB/64, 3*8), 256>>>(
            tgt, DMODEL,0, W, DMODEL,DD, (const float*)0,0,
            part, DMODEL, 0, LB, DMODEL, DMODEL, 8, 1.0f, 0);
        reduce_sk<<<(3*LB*DMODEL)/256, 256>>>(part, qkv, DMODEL, LB*DMODEL, LB, DMODEL, 8,
                                              Bi, DMODEL, 0);
        flash_attn<<<dim3(4, QT, BNH), 128, FSMEM>>>(q, k, v, part, partl,
                                                     LDQ, 4, 64, 1, qscale);
        flash_combine<<<BNH*QT, 256>>>(part, partl, ao, LDQ, 4);
        wgemm_nt<<<dim3(DMODEL/128, LB/64, 8), 256>>>(
            ao, DMODEL,0, W+3*DD, DMODEL,0, (const float*)0,0,
            part, DMODEL, 0, LB, DMODEL, DMODEL, 8, 1.0f, 0);
        reduce_ln<<<LB, DMODEL>>>(part, 8, Bi+3*DMODEL, tgt,
                                  ln_g + (size_t)(i*3+0)*DMODEL, ln_b + (size_t)(i*3+0)*DMODEL);

        // ---- cross-attention ----
        const float* Wc = ca_w + (size_t)i*4*DD;
        const float* Bc = ca_b + (size_t)i*4*DMODEL;
        bf16* ckp = ckvb + (size_t)i*CKV_L;
        bf16* cvp = ckp + (size_t)SBR*DMODEL;
        wgemm_nt<<<dim3(DMODEL/128, LB/64, 8), 256>>>(
            tgt, DMODEL,0, Wc, DMODEL,0, (const float*)0,0,
            part, DMODEL, 0, LB, DMODEL, DMODEL, 8, 1.0f, 0);
        reduce_sk<<<(LB*DMODEL)/256, 256>>>(part, q, DMODEL, 0, LB, DMODEL, 8,
                                            Bc, 0, 0);
        cudaStreamWaitEvent(0, evCkv[i], 0);
        flash_attn_bf<<<dim3(16, QT, BNH), 128, FSMEM>>>(q, ckp, cvp, CKVB_PL,
                                                         part, partl, LDQ, 16, 512, qscale);
        flash_combine<<<BNH*QT, 256>>>(part, partl, ao, LDQ, 16);
        wgemm_nt<<<dim3(DMODEL/128, LB/64, 8), 256>>>(
            ao, DMODEL,0, Wc+3*DD, DMODEL,0, (const float*)0,0,
            part, DMODEL, 0, LB, DMODEL, DMODEL, 8, 1.0f, 0);
        reduce_ln<<<LB, DMODEL>>>(part, 8, Bc+3*DMODEL, tgt,
                                  ln_g + (size_t)(i*3+1)*DMODEL, ln_b + (size_t)(i*3+1)*DMODEL);

        // ---- FFN ----
        wgemm_nt<<<dim3(DFF/128, LB/64, 1), 256>>>(
            tgt, DMODEL,0, ff_w1 + (size_t)i*DFF*DMODEL, DMODEL,0,
            ff_b1 + (size_t)i*DFF, 0,
            ffh, DFF, 0, LB, DFF, DMODEL, 1, 1.0f, 1);
        wgemm_nt<<<dim3(DMODEL/128, LB/64, 8), 256>>>(
            ffh, DFF,0, ff_w2 + (size_t)i*DMODEL*DFF, DFF,0, (const float*)0,0,
            part, DMODEL, 0, LB, DMODEL, DFF, 8, 1.0f, 0);
        reduce_ln<<<LB, DMODEL>>>(part, 8, ff_b2 + (size_t)i*DMODEL, tgt,
                                  ln_g + (size_t)(i*3+2)*DMODEL, ln_b + (size_t)(i*3+2)*DMODEL);
    }

    // final vocab projection -> d_out [L,B,V]
    gemm_nt<<<dim3((VOCAB+63)/64, LB/64), 256>>>(tgt, DMODEL, out_w, DMODEL, out_b,
                                                 out, VOCAB, LB, VOCAB, DMODEL);
}

// round 17
// speedup vs baseline: 1.0542x; 1.0009x over previous
#include <cuda_runtime.h>
#include <cuda_bf16.h>
#include <mma.h>

using namespace nvcuda;
typedef __nv_bfloat16 bf16;

// Problem constants
#define DMODEL 256
#define NHEAD  4
#define HD     64
#define NLAYER 8
#define DFF    1024
#define VOCAB  100
#define LT     256
#define BBATCH 2
#define FHH    32
#define FWW    256
#define SMEMN  (FHH*FWW)      // 8192
#define LB     (LT*BBATCH)    // 512
#define SBR    (SMEMN*BBATCH) // 16384
#define BNH    (BBATCH*NHEAD) // 8
#define LDQ    (BBATCH*DMODEL)// 512
#define QT     4              // q-tiles of 64 over LT

#define CKV_L   ((size_t)2*SBR*DMODEL)          // per-layer [ck|cv] elements
#define CKVB_PL ((size_t)NLAYER*CKV_L)          // plane offset (hi->lo)

#define LN10K 9.210340371976184f

// -------- scratch (device globals, allocation-free) --------
__device__ float g_mem[SBR*DMODEL];                    // 16 MB
__device__ __align__(16) bf16 g_ckvb[2*NLAYER*2*SBR*DMODEL];  // 268 MB bf16 hi/lo planes
__device__ float g_qkv[3*LB*DMODEL];
__device__ float g_tgt[LB*DMODEL];
__device__ float g_ao [LB*DMODEL];
__device__ float g_ffh[LB*DFF];
__device__ float g_part[4*1024*1024];                  // split-K / flash partials
__device__ float g_partl[BNH*QT*16*64];                // flash row-sum partials

__device__ __forceinline__ void split1(float v, bf16& h, bf16& l) {
    h = __float2bfloat16(v);
    l = __float2bfloat16(v - __bfloat162float(h));
}

// split a float4 into 4-element hi/lo arrays (for vector stores)
__device__ __forceinline__ void split4(float4 v, bf16* h, bf16* l) {
    split1(v.x, h[0], l[0]); split1(v.y, h[1], l[1]);
    split1(v.z, h[2], l[2]); split1(v.w, h[3], l[3]);
}

// -------- memory tensor: features + 2D PE --------
__global__ void mem_kernel(const float* __restrict__ features, float* __restrict__ mem) {
    int idx = blockIdx.x * 256 + threadIdx.x;
    int c   = idx & (DMODEL-1);
    int row = idx >> 8;
    int b   = row & (BBATCH-1);
    int s   = row >> 1;
    int h   = s / FWW;
    int w   = s % FWW;
    float pe;
    if (c < DMODEL/2) {
        int e = c & ~1;
        float dv = __expf(-(float)e / (float)DMODEL * LN10K);
        float arg = (float)h * dv;
        pe = (c & 1) ? cosf(arg) : sinf(arg);
    } else {
        int e = (c - DMODEL/2) & ~1;
        float dv = __expf(-(float)e / (float)DMODEL * LN10K);
        float arg = (float)w * dv;
        pe = (c & 1) ? cosf(arg) : sinf(arg);
    }
    mem[idx] = features[(((size_t)b*DMODEL + c)*FHH + h)*FWW + w] + pe;
}

// -------- embedding + 1D PE --------
__global__ void embed_kernel(const int* __restrict__ tokens, const float* __restrict__ emb,
                             float* __restrict__ tgt) {
    int idx = blockIdx.x * 256 + threadIdx.x;
    int c   = idx & (DMODEL-1);
    int row = idx >> 8;
    int l   = row >> 1;
    int tok = tokens[row];
    int e = c & ~1;
    float dv = __expf(-(float)e / (float)DMODEL * LN10K);
    float arg = (float)l * dv;
    float pe = (c & 1) ? cosf(arg) : sinf(arg);
    tgt[idx] = emb[(size_t)tok*DMODEL + c] + pe;
}

// ============================================================================
// bf16x3 NT GEMM (R14-proven, BK=16, fp32-only epilogue — main chain).
// ============================================================================
__global__ __launch_bounds__(256) void wgemm_nt(
    const float* __restrict__ A, int lda, int aB,
    const float* __restrict__ Bm, int ldb, int bB,
    const float* __restrict__ bias, int biasB,
    float* __restrict__ C, int ldc, int cB,
    int M, int N, int K, int ksplit, float scale, int relu)
{
    __shared__ __align__(16) char smem_u[64*132*4];
    bf16 (*Ah)[24] = (bf16(*)[24])smem_u;
    bf16 (*Al)[24] = (bf16(*)[24])(smem_u + 3072);
    bf16 (*Bh)[24] = (bf16(*)[24])(smem_u + 6144);
    bf16 (*Bl)[24] = (bf16(*)[24])(smem_u + 12288);
    float (*Os)[132] = (float(*)[132])smem_u;

    int ks = blockIdx.z % ksplit, batch = blockIdx.z / ksplit;
    A  += (size_t)batch * aB;
    Bm += (size_t)batch * bB;
    if (ksplit > 1) {
        C += (size_t)blockIdx.z * M * N;
    } else {
        C += (size_t)batch * cB;
        if (bias) bias += (size_t)batch * biasB;
    }
    int row0 = blockIdx.y * 64, col0 = blockIdx.x * 128;
    int tid = threadIdx.x;
    int wid = tid >> 5;
    int wm = wid >> 2, wn = wid & 3;

    wmma::fragment<wmma::accumulator, 16,16,16, float> cf[2][2];
    #pragma unroll
    for (int i=0;i<2;i++)
        #pragma unroll
        for (int j=0;j<2;j++) wmma::fill_fragment(cf[i][j], 0.0f);

    int kbeg = ks * (K/ksplit), kend = kbeg + K/ksplit;
    int am = tid >> 2, ac = (tid & 3) * 4;

    for (int k0 = kbeg; k0 < kend; k0 += 16) {
        {
            bf16 hv[4], lv[4];
            split4(*(const float4*)&A[(size_t)(row0+am)*lda + k0 + ac], hv, lv);
            *(uint2*)&Ah[am][ac] = *(uint2*)hv;
            *(uint2*)&Al[am][ac] = *(uint2*)lv;
            split4(*(const float4*)&Bm[(size_t)(col0+am)*ldb + k0 + ac], hv, lv);
            *(uint2*)&Bh[am][ac] = *(uint2*)hv;
            *(uint2*)&Bl[am][ac] = *(uint2*)lv;
            split4(*(const float4*)&Bm[(size_t)(col0+am+64)*ldb + k0 + ac], hv, lv);
            *(uint2*)&Bh[am+64][ac] = *(uint2*)hv;
            *(uint2*)&Bl[am+64][ac] = *(uint2*)lv;
        }
        __syncthreads();
        wmma::fragment<wmma::matrix_a, 16,16,16, bf16, wmma::row_major> ah[2], al[2];
        wmma::fragment<wmma::matrix_b, 16,16,16, bf16, wmma::col_major> bh[2], bl[2];
        #pragma unroll
        for (int i=0;i<2;i++) {
            wmma::load_matrix_sync(ah[i], &Ah[wm*32 + i*16][0], 24);
            wmma::load_matrix_sync(al[i], &Al[wm*32 + i*16][0], 24);
        }
        #pragma unroll
        for (int j=0;j<2;j++) {
            wmma::load_matrix_sync(bh[j], &Bh[wn*32 + j*16][0], 24);
            wmma::load_matrix_sync(bl[j], &Bl[wn*32 + j*16][0], 24);
        }
        #pragma unroll
        for (int i=0;i<2;i++)
            #pragma unroll
            for (int j=0;j<2;j++) {
                wmma::mma_sync(cf[i][j], ah[i], bh[j], cf[i][j]);
                wmma::mma_sync(cf[i][j], ah[i], bl[j], cf[i][j]);
                wmma::mma_sync(cf[i][j], al[i], bh[j], cf[i][j]);
            }
        __syncthreads();
    }

    #pragma unroll
    for (int i=0;i<2;i++)
        #pragma unroll
        for (int j=0;j<2;j++)
            wmma::store_matrix_sync(&Os[wm*32+i*16][wn*32+j*16], cf[i][j], 132, wmma::mem_row_major);
    __syncthreads();

    #pragma unroll
    for (int it = 0; it < 8; it++) {
        int idx = it*256 + tid;
        int m = idx >> 5;
        int c4 = (idx & 31) * 4;
        float4 v = *(float4*)&Os[m][c4];
        if (ksplit == 1) {
            if (bias) {
                v.x += bias[col0+c4];   v.y += bias[col0+c4+1];
                v.z += bias[col0+c4+2]; v.w += bias[col0+c4+3];
            }
            v.x *= scale; v.y *= scale; v.z *= scale; v.w *= scale;
            if (relu) {
                v.x = fmaxf(v.x, 0.f); v.y = fmaxf(v.y, 0.f);
                v.z = fmaxf(v.z, 0.f); v.w = fmaxf(v.w, 0.f);
            }
            *(float4*)&C[(size_t)(row0+m)*ldc + col0 + c4] = v;
        } else {
            *(float4*)&C[(size_t)(row0+m)*N + col0 + c4] = v;
        }
    }
}

// ============================================================================
// Side-stream-only clone: bf16 hi/lo plane output (ckv producer).
// ============================================================================
__global__ __launch_bounds__(256) void wgemm_nt_ckv(
    const float* __restrict__ A, int lda,
    const float* __restrict__ Bm, int ldb, int bB,
    const float* __restrict__ bias, int biasB,
    bf16* __restrict__ Cb, size_t cPlane, int ldc, int cB,
    int M, int N, int K)
{
    __shared__ __align__(16) char smem_u[64*132*4];
    bf16 (*Ah)[24] = (bf16(*)[24])smem_u;
    bf16 (*Al)[24] = (bf16(*)[24])(smem_u + 3072);
    bf16 (*Bh)[24] = (bf16(*)[24])(smem_u + 6144);
    bf16 (*Bl)[24] = (bf16(*)[24])(smem_u + 12288);
    float (*Os)[132] = (float(*)[132])smem_u;

    int batch = blockIdx.z;
    Bm   += (size_t)batch * bB;
    Cb   += (size_t)batch * cB;
    bias += (size_t)batch * biasB;
    int row0 = blockIdx.y * 64, col0 = blockIdx.x * 128;
    int tid = threadIdx.x;
    int wid = tid >> 5;
    int wm = wid >> 2, wn = wid & 3;

    wmma::fragment<wmma::accumulator, 16,16,16, float> cf[2][2];
    #pragma unroll
    for (int i=0;i<2;i++)
        #pragma unroll
        for (int j=0;j<2;j++) wmma::fill_fragment(cf[i][j], 0.0f);

    int am = tid >> 2, ac = (tid & 3) * 4;

    for (int k0 = 0; k0 < K; k0 += 16) {
        {
            bf16 hv[4], lv[4];
            split4(*(const float4*)&A[(size_t)(row0+am)*lda + k0 + ac], hv, lv);
            *(uint2*)&Ah[am][ac] = *(uint2*)hv;
            *(uint2*)&Al[am][ac] = *(uint2*)lv;
            split4(*(const float4*)&Bm[(size_t)(col0+am)*ldb + k0 + ac], hv, lv);
            *(uint2*)&Bh[am][ac] = *(uint2*)hv;
            *(uint2*)&Bl[am][ac] = *(uint2*)lv;
            split4(*(const float4*)&Bm[(size_t)(col0+am+64)*ldb + k0 + ac], hv, lv);
            *(uint2*)&Bh[am+64][ac] = *(uint2*)hv;
            *(uint2*)&Bl[am+64][ac] = *(uint2*)lv;
        }
        __syncthreads();
        wmma::fragment<wmma::matrix_a, 16,16,16, bf16, wmma::row_major> ah[2], al[2];
        wmma::fragment<wmma::matrix_b, 16,16,16, bf16, wmma::col_major> bh[2], bl[2];
        #pragma unroll
        for (int i=0;i<2;i++) {
            wmma::load_matrix_sync(ah[i], &Ah[wm*32 + i*16][0], 24);
            wmma::load_matrix_sync(al[i], &Al[wm*32 + i*16][0], 24);
        }
        #pragma unroll
        for (int j=0;j<2;j++) {
            wmma::load_matrix_sync(bh[j], &Bh[wn*32 + j*16][0], 24);
            wmma::load_matrix_sync(bl[j], &Bl[wn*32 + j*16][0], 24);
        }
        #pragma unroll
        for (int i=0;i<2;i++)
            #pragma unroll
            for (int j=0;j<2;j++) {
                wmma::mma_sync(cf[i][j], ah[i], bh[j], cf[i][j]);
                wmma::mma_sync(cf[i][j], ah[i], bl[j], cf[i][j]);
                wmma::mma_sync(cf[i][j], al[i], bh[j], cf[i][j]);
            }
        __syncthreads();
    }

    #pragma unroll
    for (int i=0;i<2;i++)
        #pragma unroll
        for (int j=0;j<2;j++)
            wmma::store_matrix_sync(&Os[wm*32+i*16][wn*32+j*16], cf[i][j], 132, wmma::mem_row_major);
    __syncthreads();

    #pragma unroll
    for (int it = 0; it < 8; it++) {
        int idx = it*256 + tid;
        int m = idx >> 5;
        int c4 = (idx & 31) * 4;
        float4 v = *(float4*)&Os[m][c4];
        v.x += bias[col0+c4];   v.y += bias[col0+c4+1];
        v.z += bias[col0+c4+2]; v.w += bias[col0+c4+3];
        size_t o = (size_t)(row0+m)*ldc + col0 + c4;
        bf16 hv[4], lv[4];
        split4(v, hv, lv);
        *(uint2*)&Cb[o] = *(uint2*)hv;
        *(uint2*)&Cb[cPlane + o] = *(uint2*)lv;
    }
}

// -------- split-K reduce (plain fp32 out) --------
__global__ void reduce_sk(const float* __restrict__ P, float* __restrict__ C,
                          int ldc, int cB, int M, int N, int ksplit,
                          const float* __restrict__ bias, int biasB, int relu)
{
    int idx = blockIdx.x * 256 + threadIdx.x;
    int n = idx % N;
    int mb = idx / N;
    int m = mb % M;
    int batch = mb / M;
    const float* p = P + ((size_t)batch*ksplit)*M*N + (size_t)m*N + n;
    float s = 0.0f;
    for (int ksi = 0; ksi < ksplit; ksi++) s += p[(size_t)ksi*M*N];
    if (bias) s += bias[(size_t)batch*biasB + n];
    if (relu) s = fmaxf(s, 0.0f);
    C[(size_t)batch*cB + (size_t)m*ldc + n] = s;
}

// -------- FUSED: split-K reduce + bias + residual + LayerNorm (in-place tgt) ----
__global__ void reduce_ln(const float* __restrict__ P, int ksplit,
                          const float* __restrict__ bias,
                          float* __restrict__ tgt,
                          const float* __restrict__ g, const float* __restrict__ b)
{
    __shared__ float shm[8];
    int row = blockIdx.x, c = threadIdx.x;
    size_t idx = (size_t)row * DMODEL + c;
    float s = 0.0f;
    for (int ksi = 0; ksi < ksplit; ksi++) s += P[(size_t)ksi*LB*DMODEL + idx];
    s += bias[c];
    float x = tgt[idx] + s;

    float t = x;
    for (int o = 16; o; o >>= 1) t += __shfl_xor_sync(0xffffffffu, t, o);
    if ((c & 31) == 0) shm[c >> 5] = t;
    __syncthreads();
    if (c < 32) {
        float u = (c < 8) ? shm[c] : 0.0f;
        for (int o = 4; o; o >>= 1) u += __shfl_xor_sync(0xffffffffu, u, o);
        if (c == 0) shm[0] = u;
    }
    __syncthreads();
    float mean = shm[0] * (1.0f / DMODEL);
    __syncthreads();

    float d0 = x - mean;
    t = d0 * d0;
    for (int o = 16; o; o >>= 1) t += __shfl_xor_sync(0xffffffffu, t, o);
    if ((c & 31) == 0) shm[c >> 5] = t;
    __syncthreads();
    if (c < 32) {
        float u = (c < 8) ? shm[c] : 0.0f;
        for (int o = 4; o; o >>= 1) u += __shfl_xor_sync(0xffffffffu, u, o);
        if (c == 0) shm[0] = u;
    }
    __syncthreads();
    float var = shm[0] * (1.0f / DMODEL);
    tgt[idx] = d0 * rsqrtf(var + 1e-5f) * g[c] + b[c];
}

// ============================================================================
// Fused flash attention, fp32 inputs (self-attention).
// Vectorized staging stores + vectorized exp phase.
// ============================================================================
#define FSMEM 91904
__global__ __launch_bounds__(128) void flash_attn(
    const float* __restrict__ Q, const float* __restrict__ K, const float* __restrict__ V,
    float* __restrict__ pO, float* __restrict__ pL,
    int ldq, int SP, int Schunk, int causal, float qscale)
{
    extern __shared__ char fsm[];
    bf16 (*Qh)[72] = (bf16(*)[72])(fsm);
    bf16 (*Ql)[72] = (bf16(*)[72])(fsm + 9216);
    bf16 (*Kh)[72] = (bf16(*)[72])(fsm + 18432);
    bf16 (*Kl)[72] = (bf16(*)[72])(fsm + 27648);
    bf16 (*Vh)[72] = (bf16(*)[72])(fsm + 36864);
    bf16 (*Vl)[72] = (bf16(*)[72])(fsm + 46080);
    float (*Ssm)[68] = (float(*)[68])(fsm + 55296);
    bf16 (*Ph)[72] = (bf16(*)[72])(fsm + 72704);
    bf16 (*Pl)[72] = (bf16(*)[72])(fsm + 81920);
    float* rs    = (float*)(fsm + 91136);
    float* rsum2 = (float*)(fsm + 91392);

    int sp = blockIdx.x, qt = blockIdx.y, n = blockIdx.z;
    int tid = threadIdx.x;
    int wid = tid >> 5;
    int wm = wid >> 1, wn = wid & 1;
    int pidx = (n*QT + qt)*SP + sp;
    int q0 = qt*64;
    int s0 = sp*Schunk;

    if (causal && s0 > q0 + 63) {
        for (int i = tid; i < 64*64; i += 128) pO[(size_t)pidx*4096 + i] = 0.f;
        if (tid < 64) pL[pidx*64 + tid] = 0.f;
        return;
    }

    const float* Qb = Q + (size_t)n*HD;
    const float* Kb = K + (size_t)n*HD;
    const float* Vb = V + (size_t)n*HD;

    #pragma unroll
    for (int it = 0; it < 8; it++) {
        int idx = it*128 + tid;
        int r = idx >> 4, c4 = (idx & 15)*4;
        bf16 hv[4], lv[4];
        split4(*(const float4*)&Qb[(size_t)(q0+r)*ldq + c4], hv, lv);
        *(uint2*)&Qh[r][c4] = *(uint2*)hv;
        *(uint2*)&Ql[r][c4] = *(uint2*)lv;
    }
    if (tid < 64) rs[tid] = 0.f;

    wmma::fragment<wmma::accumulator, 16,16,16, float> of[2][2];
    #pragma unroll
    for (int i=0;i<2;i++)
        #pragma unroll
        for (int j=0;j<2;j++) wmma::fill_fragment(of[i][j], 0.0f);

    int ntile = Schunk / 64;
    for (int t = 0; t < ntile; t++) {
        int sbase = s0 + t*64;
        if (causal && sbase > q0 + 63) break;
        __syncthreads();
        #pragma unroll
        for (int it = 0; it < 8; it++) {
            int idx = it*128 + tid;
            int r = idx >> 4, c4 = (idx & 15)*4;
            bf16 hv[4], lv[4];
            split4(*(const float4*)&Kb[(size_t)(sbase+r)*ldq + c4], hv, lv);
            *(uint2*)&Kh[r][c4] = *(uint2*)hv;
            *(uint2*)&Kl[r][c4] = *(uint2*)lv;
            split4(*(const float4*)&Vb[(size_t)(sbase+r)*ldq + c4], hv, lv);
            *(uint2*)&Vh[r][c4] = *(uint2*)hv;
            *(uint2*)&Vl[r][c4] = *(uint2*)lv;
        }
        __syncthreads();

        wmma::fragment<wmma::accumulator, 16,16,16, float> sf[2][2];
        #pragma unroll
        for (int i=0;i<2;i++)
            #pragma unroll
            for (int j=0;j<2;j++) wmma::fill_fragment(sf[i][j], 0.0f);
        #pragma unroll
        for (int kk = 0; kk < 4; kk++) {
            wmma::fragment<wmma::matrix_a, 16,16,16, bf16, wmma::row_major> ah[2], al[2];
            wmma::fragment<wmma::matrix_b, 16,16,16, bf16, wmma::col_major> bh[2], bl[2];
            #pragma unroll
            for (int i=0;i<2;i++) {
                wmma::load_matrix_sync(ah[i], &Qh[wm*32 + i*16][kk*16], 72);
                wmma::load_matrix_sync(al[i], &Ql[wm*32 + i*16][kk*16], 72);
            }
            #pragma unroll
            for (int j=0;j<2;j++) {
                wmma::load_matrix_sync(bh[j], &Kh[wn*32 + j*16][kk*16], 72);
                wmma::load_matrix_sync(bl[j], &Kl[wn*32 + j*16][kk*16], 72);
            }
            #pragma unroll
            for (int i=0;i<2;i++)
                #pragma unroll
                for (int j=0;j<2;j++) {
                    wmma::mma_sync(sf[i][j], ah[i], bh[j], sf[i][j]);
                    wmma::mma_sync(sf[i][j], ah[i], bl[j], sf[i][j]);
                    wmma::mma_sync(sf[i][j], al[i], bh[j], sf[i][j]);
                }
        }
        #pragma unroll
        for (int i=0;i<2;i++)
            #pragma unroll
            for (int j=0;j<2;j++)
                wmma::store_matrix_sync(&Ssm[wm*32+i*16][wn*32+j*16], sf[i][j], 68, wmma::mem_row_major);
        __syncthreads();

        // exp + P planes (vectorized: float4 loads, uint4 stores)
        {
            int r = tid >> 1, cbeg = (tid & 1) * 32;
            float psum = 0.f;
            #pragma unroll
            for (int c8 = 0; c8 < 32; c8 += 8) {
                float4 x0 = *(float4*)&Ssm[r][cbeg + c8];
                float4 x1 = *(float4*)&Ssm[r][cbeg + c8 + 4];
                float e[8];
                e[0]=__expf(x0.x*qscale); e[1]=__expf(x0.y*qscale);
                e[2]=__expf(x0.z*qscale); e[3]=__expf(x0.w*qscale);
                e[4]=__expf(x1.x*qscale); e[5]=__expf(x1.y*qscale);
                e[6]=__expf(x1.z*qscale); e[7]=__expf(x1.w*qscale);
                if (causal) {
                    #pragma unroll
                    for (int u = 0; u < 8; u++)
                        if (sbase + cbeg + c8 + u > q0 + r) e[u] = 0.f;
                }
                bf16 hv[8], lv[8];
                #pragma unroll
                for (int u = 0; u < 8; u++) {
                    psum += e[u];
                    split1(e[u], hv[u], lv[u]);
                }
                *(uint4*)&Ph[r][cbeg + c8] = *(uint4*)hv;
                *(uint4*)&Pl[r][cbeg + c8] = *(uint4*)lv;
            }
            rsum2[tid] = psum;
        }
        __syncthreads();
        if (tid < 64) rs[tid] += rsum2[tid*2] + rsum2[tid*2+1];

        #pragma unroll
        for (int kk = 0; kk < 4; kk++) {
            wmma::fragment<wmma::matrix_a, 16,16,16, bf16, wmma::row_major> ah[2], al[2];
            wmma::fragment<wmma::matrix_b, 16,16,16, bf16, wmma::row_major> bh[2], bl[2];
            #pragma unroll
            for (int i=0;i<2;i++) {
                wmma::load_matrix_sync(ah[i], &Ph[wm*32 + i*16][kk*16], 72);
                wmma::load_matrix_sync(al[i], &Pl[wm*32 + i*16][kk*16], 72);
            }
            #pragma unroll
            for (int j=0;j<2;j++) {
                wmma::load_matrix_sync(bh[j], &Vh[kk*16][wn*32 + j*16], 72);
                wmma::load_matrix_sync(bl[j], &Vl[kk*16][wn*32 + j*16], 72);
            }
            #pragma unroll
            for (int i=0;i<2;i++)
                #pragma unroll
                for (int j=0;j<2;j++) {
                    wmma::mma_sync(of[i][j], ah[i], bh[j], of[i][j]);
                    wmma::mma_sync(of[i][j], ah[i], bl[j], of[i][j]);
                    wmma::mma_sync(of[i][j], al[i], bh[j], of[i][j]);
                }
        }
    }

    __syncthreads();
    #pragma unroll
    for (int i=0;i<2;i++)
        #pragma unroll
        for (int j=0;j<2;j++)
            wmma::store_matrix_sync(&Ssm[wm*32+i*16][wn*32+j*16], of[i][j], 68, wmma::mem_row_major);
    __syncthreads();

    float* po = pO + (size_t)pidx*4096;
    #pragma unroll
    for (int it = 0; it < 8; it++) {
        int idx = it*128 + tid;
        int r = idx >> 4, c4 = (idx & 15)*4;
        float4 v = make_float4(Ssm[r][c4], Ssm[r][c4+1], Ssm[r][c4+2], Ssm[r][c4+3]);
        *(float4*)&po[r*64 + c4] = v;
    }
    if (tid < 64) pL[pidx*64 + tid] = rs[tid];
}

// ============================================================================
// Fused flash attention, PRE-SPLIT bf16 K/V planes (cross-attention).
// Pure-copy K/V staging; vectorized exp phase.
// ============================================================================
__global__ __launch_bounds__(128) void flash_attn_bf(
    const float* __restrict__ Q,
    const bf16* __restrict__ K, const bf16* __restrict__ V, size_t kvPlane,
    float* __restrict__ pO, float* __restrict__ pL,
    int ldq, int SP, int Schunk, float qscale)
{
    extern __shared__ char fsm[];
    bf16 (*Qh)[72] = (bf16(*)[72])(fsm);
    bf16 (*Ql)[72] = (bf16(*)[72])(fsm + 9216);
    bf16 (*Kh)[72] = (bf16(*)[72])(fsm + 18432);
    bf16 (*Kl)[72] = (bf16(*)[72])(fsm + 27648);
    bf16 (*Vh)[72] = (bf16(*)[72])(fsm + 36864);
    bf16 (*Vl)[72] = (bf16(*)[72])(fsm + 46080);
    float (*Ssm)[68] = (float(*)[68])(fsm + 55296);
    bf16 (*Ph)[72] = (bf16(*)[72])(fsm + 72704);
    bf16 (*Pl)[72] = (bf16(*)[72])(fsm + 81920);
    float* rs    = (float*)(fsm + 91136);
    float* rsum2 = (float*)(fsm + 91392);

    int sp = blockIdx.x, qt = blockIdx.y, n = blockIdx.z;
    int tid = threadIdx.x;
    int wid = tid >> 5;
    int wm = wid >> 1, wn = wid & 1;
    int pidx = (n*QT + qt)*SP + sp;
    int q0 = qt*64;
    int s0 = sp*Schunk;

    const float* Qb = Q + (size_t)n*HD;
    const bf16*  Kb = K + (size_t)n*HD;
    const bf16*  Vb = V + (size_t)n*HD;

    #pragma unroll
    for (int it = 0; it < 8; it++) {
        int idx = it*128 + tid;
        int r = idx >> 4, c4 = (idx & 15)*4;
        bf16 hv[4], lv[4];
        split4(*(const float4*)&Qb[(size_t)(q0+r)*ldq + c4], hv, lv);
        *(uint2*)&Qh[r][c4] = *(uint2*)hv;
        *(uint2*)&Ql[r][c4] = *(uint2*)lv;
    }
    if (tid < 64) rs[tid] = 0.f;

    wmma::fragment<wmma::accumulator, 16,16,16, float> of[2][2];
    #pragma unroll
    for (int i=0;i<2;i++)
        #pragma unroll
        for (int j=0;j<2;j++) wmma::fill_fragment(of[i][j], 0.0f);

    int ntile = Schunk / 64;
    for (int t = 0; t < ntile; t++) {
        int sbase = s0 + t*64;
        __syncthreads();
        // pure copy staging: 64 rows x 8 float4-slots (8 bf16 each)
        #pragma unroll
        for (int it = 0; it < 4; it++) {
            int idx = it*128 + tid;
            int r = idx >> 3, c8 = (idx & 7)*8;
            size_t ro = (size_t)(sbase+r)*ldq + c8;
            *(float4*)&Kh[r][c8] = *(const float4*)&Kb[ro];
            *(float4*)&Kl[r][c8] = *(const float4*)&Kb[kvPlane + ro];
            *(float4*)&Vh[r][c8] = *(const float4*)&Vb[ro];
            *(float4*)&Vl[r][c8] = *(const float4*)&Vb[kvPlane + ro];
        }
        __syncthreads();

        wmma::fragment<wmma::accumulator, 16,16,16, float> sf[2][2];
        #pragma unroll
        for (int i=0;i<2;i++)
            #pragma unroll
            for (int j=0;j<2;j++) wmma::fill_fragment(sf[i][j], 0.0f);
        #pragma unroll
        for (int kk = 0; kk < 4; kk++) {
            wmma::fragment<wmma::matrix_a, 16,16,16, bf16, wmma::row_major> ah[2], al[2];
            wmma::fragment<wmma::matrix_b, 16,16,16, bf16, wmma::col_major> bh[2], bl[2];
            #pragma unroll
            for (int i=0;i<2;i++) {
                wmma::load_matrix_sync(ah[i], &Qh[wm*32 + i*16][kk*16], 72);
                wmma::load_matrix_sync(al[i], &Ql[wm*32 + i*16][kk*16], 72);
            }
            #pragma unroll
            for (int j=0;j<2;j++) {
                wmma::load_matrix_sync(bh[j], &Kh[wn*32 + j*16][kk*16], 72);
                wmma::load_matrix_sync(bl[j], &Kl[wn*32 + j*16][kk*16], 72);
            }
            #pragma unroll
            for (int i=0;i<2;i++)
                #pragma unroll
                for (int j=0;j<2;j++) {
                    wmma::mma_sync(sf[i][j], ah[i], bh[j], sf[i][j]);
                    wmma::mma_sync(sf[i][j], ah[i], bl[j], sf[i][j]);
                    wmma::mma_sync(sf[i][j], al[i], bh[j], sf[i][j]);
                }
        }
        #pragma unroll
        for (int i=0;i<2;i++)
            #pragma unroll
            for (int j=0;j<2;j++)
                wmma::store_matrix_sync(&Ssm[wm*32+i*16][wn*32+j*16], sf[i][j], 68, wmma::mem_row_major);
        __syncthreads();

        // exp + P planes (vectorized)
        {
            int r = tid >> 1, cbeg = (tid & 1) * 32;
            float psum = 0.f;
            #pragma unroll
            for (int c8 = 0; c8 < 32; c8 += 8) {
                float4 x0 = *(float4*)&Ssm[r][cbeg + c8];
                float4 x1 = *(float4*)&Ssm[r][cbeg + c8 + 4];
                float e[8];
                e[0]=__expf(x0.x*qscale); e[1]=__expf(x0.y*qscale);
                e[2]=__expf(x0.z*qscale); e[3]=__expf(x0.w*qscale);
                e[4]=__expf(x1.x*qscale); e[5]=__expf(x1.y*qscale);
                e[6]=__expf(x1.z*qscale); e[7]=__expf(x1.w*qscale);
                bf16 hv[8], lv[8];
                #pragma unroll
                for (int u = 0; u < 8; u++) {
                    psum += e[u];
                    split1(e[u], hv[u], lv[u]);
                }
                *(uint4*)&Ph[r][cbeg + c8] = *(uint4*)hv;
                *(uint4*)&Pl[r][cbeg + c8] = *(uint4*)lv;
            }
            rsum2[tid] = psum;
        }
        __syncthreads();
        if (tid < 64) rs[tid] += rsum2[tid*2] + rsum2[tid*2+1];

        #pragma unroll
        for (int kk = 0; kk < 4; kk++) {
            wmma::fragment<wmma::matrix_a, 16,16,16, bf16, wmma::row_major> ah[2], al[2];
            wmma::fragment<wmma::matrix_b, 16,16,16, bf16, wmma::row_major> bh[2], bl[2];
            #pragma unroll
            for (int i=0;i<2;i++) {
                wmma::load_matrix_sync(ah[i], &Ph[wm*32 + i*16][kk*16], 72);
                wmma::load_matrix_sync(al[i], &Pl[wm*32 + i*16][kk*16], 72);
            }
            #pragma unroll
            for (int j=0;j<2;j++) {
                wmma::load_matrix_sync(bh[j], &Vh[kk*16][wn*32 + j*16], 72);
                wmma::load_matrix_sync(bl[j], &Vl[kk*16][wn*32 + j*16], 72);
            }
            #pragma unroll
            for (int i=0;i<2;i++)
                #pragma unroll
                for (int j=0;j<2;j++) {
                    wmma::mma_sync(of[i][j], ah[i], bh[j], of[i][j]);
                    wmma::mma_sync(of[i][j], ah[i], bl[j], of[i][j]);
                    wmma::mma_sync(of[i][j], al[i], bh[j], of[i][j]);
                }
        }
    }

    __syncthreads();
    #pragma unroll
    for (int i=0;i<2;i++)
        #pragma unroll
        for (int j=0;j<2;j++)
            wmma::store_matrix_sync(&Ssm[wm*32+i*16][wn*32+j*16], of[i][j], 68, wmma::mem_row_major);
    __syncthreads();

    float* po = pO + (size_t)pidx*4096;
    #pragma unroll
    for (int it = 0; it < 8; it++) {
        int idx = it*128 + tid;
        int r = idx >> 4, c4 = (idx & 15)*4;
        float4 v = make_float4(Ssm[r][c4], Ssm[r][c4+1], Ssm[r][c4+2], Ssm[r][c4+3]);
        *(float4*)&po[r*64 + c4] = v;
    }
    if (tid < 64) pL[pidx*64 + tid] = rs[tid];
}

// -------- combine flash partials: ao = sum_sp O_sp / sum_sp l_sp --------
__global__ void flash_combine(const float* __restrict__ pO, const float* __restrict__ pL,
                              float* __restrict__ ao, int ldq, int SP)
{
    int nq = blockIdx.x;
    int n = nq >> 2, qt = nq & 3;
    int q0 = qt*64;
    #pragma unroll
    for (int it = 0; it < 16; it++) {
        int idx = it*256 + threadIdx.x;
        int r = idx >> 6, c = idx & 63;
        float osum = 0.f, lsum = 0.f;
        for (int sp = 0; sp < SP; sp++) {
            int p = nq*SP + sp;
            osum += pO[(size_t)p*4096 + idx];
            lsum += pL[p*64 + r];
        }
        ao[(size_t)(q0+r)*ldq + n*HD + c] = osum / lsum;
    }
}

// -------- SIMT NT GEMM (vocab projection only) --------
__global__ __launch_bounds__(256) void gemm_nt(
    const float* __restrict__ A, int lda,
    const float* __restrict__ Bm, int ldb,
    const float* __restrict__ bias,
    float* __restrict__ C, int ldc,
    int M, int N, int K)
{
    __shared__ float As[16][68];
    __shared__ float Bs[16][68];
    int row0 = blockIdx.y * 64, col0 = blockIdx.x * 64;
    int tid = threadIdx.x;
    int tx = tid & 15, ty = tid >> 4;
    int lc = tid & 15, lr = tid >> 4;
    float acc[4][4] = {};
    for (int k0 = 0; k0 < K; k0 += 16) {
        #pragma unroll
        for (int it = 0; it < 4; it++)
            As[lc][lr + it*16] = A[(size_t)(row0 + lr + it*16) * lda + k0 + lc];
        #pragma unroll
        for (int it = 0; it < 4; it++) {
            int n = col0 + lr + it*16;
            Bs[lc][lr + it*16] = (n < N) ? Bm[(size_t)n * ldb + k0 + lc] : 0.0f;
        }
        __syncthreads();
        #pragma unroll
        for (int kk = 0; kk < 16; kk++) {
            float4 av = *(const float4*)&As[kk][ty*4];
            float4 bv = *(const float4*)&Bs[kk][tx*4];
            acc[0][0] += av.x*bv.x; acc[0][1] += av.x*bv.y; acc[0][2] += av.x*bv.z; acc[0][3] += av.x*bv.w;
            acc[1][0] += av.y*bv.x; acc[1][1] += av.y*bv.y; acc[1][2] += av.y*bv.z; acc[1][3] += av.y*bv.w;
            acc[2][0] += av.z*bv.x; acc[2][1] += av.z*bv.y; acc[2][2] += av.z*bv.z; acc[2][3] += av.z*bv.w;
            acc[3][0] += av.w*bv.x; acc[3][1] += av.w*bv.y; acc[3][2] += av.w*bv.z; acc[3][3] += av.w*bv.w;
        }
        __syncthreads();
    }
    #pragma unroll
    for (int i = 0; i < 4; i++) {
        int m = row0 + ty*4 + i;
        #pragma unroll
        for (int j = 0; j < 4; j++) {
            int n = col0 + tx*4 + j;
            if (n < N) C[(size_t)m*ldc + n] = acc[i][j] + bias[n];
        }
    }
}

extern "C" void kernel_launch(void* const* d_in, const int* in_sizes, int n_in,
                              void* d_out, int out_size) {
    const int*   tokens   = (const int*)  d_in[0];
    const float* features = (const float*)d_in[1];
    const float* emb      = (const float*)d_in[2];
    const float* sa_w     = (const float*)d_in[3];
    const float* sa_b     = (const float*)d_in[4];
    const float* ca_w     = (const float*)d_in[5];
    const float* ca_b     = (const float*)d_in[6];
    const float* ln_g     = (const float*)d_in[7];
    const float* ln_b     = (const float*)d_in[8];
    const float* ff_w1    = (const float*)d_in[9];
    const float* ff_b1    = (const float*)d_in[10];
    const float* ff_w2    = (const float*)d_in[11];
    const float* ff_b2    = (const float*)d_in[12];
    const float* out_w    = (const float*)d_in[13];
    const float* out_b    = (const float*)d_in[14];
    float* out = (float*)d_out;

    float *mem, *qkv, *tgt, *ao, *ffh, *part, *partl;
    bf16 *ckvb;
    cudaGetSymbolAddress((void**)&mem,  g_mem);
    cudaGetSymbolAddress((void**)&ckvb, g_ckvb);
    cudaGetSymbolAddress((void**)&qkv,  g_qkv);
    cudaGetSymbolAddress((void**)&tgt,  g_tgt);
    cudaGetSymbolAddress((void**)&ao,   g_ao);
    cudaGetSymbolAddress((void**)&ffh,  g_ffh);
    cudaGetSymbolAddress((void**)&part, g_part);
    cudaGetSymbolAddress((void**)&partl,g_partl);

    cudaFuncSetAttribute(flash_attn,    cudaFuncAttributeMaxDynamicSharedMemorySize, FSMEM);
    cudaFuncSetAttribute(flash_attn_bf, cudaFuncAttributeMaxDynamicSharedMemorySize, FSMEM);

    static cudaStream_t s2 = nullptr;
    static cudaEvent_t evRoot = nullptr;
    static cudaEvent_t evCkv[NLAYER];
    if (!s2) {
        cudaStreamCreateWithFlags(&s2, cudaStreamNonBlocking);
        cudaEventCreateWithFlags(&evRoot, cudaEventDisableTiming);
        for (int i = 0; i < NLAYER; i++)
            cudaEventCreateWithFlags(&evCkv[i], cudaEventDisableTiming);
    }

    float* q = qkv;
    float* k = qkv + (size_t)LB*DMODEL;
    float* v = qkv + (size_t)2*LB*DMODEL;

    const float qscale = 0.125f;
    const int DD = DMODEL*DMODEL;

    mem_kernel<<<(SBR*DMODEL)/256, 256>>>(features, mem);
    cudaEventRecord(evRoot, 0);

    cudaStreamWaitEvent(s2, evRoot, 0);
    for (int i = 0; i < NLAYER; i++) {
        wgemm_nt_ckv<<<dim3(DMODEL/128, SBR/64, 2), 256, 0, s2>>>(
            mem, DMODEL,
            ca_w + (size_t)i*4*DD + DD, DMODEL, DD,
            ca_b + (size_t)i*4*DMODEL + DMODEL, DMODEL,
            ckvb + (size_t)i*CKV_L, CKVB_PL, DMODEL, SBR*DMODEL,
            SBR, DMODEL, DMODEL);
        cudaEventRecord(evCkv[i], s2);
    }

    embed_kernel<<<(LB*DMODEL)/256, 256>>>(tokens, emb, tgt);

    for (int i = 0; i < NLAYER; i++) {
        const float* W  = sa_w + (size_t)i*4*DD;
        const float* Bi = sa_b + (size_t)i*4*DMODEL;

        // ---- self-attention ----
        wgemm_nt<<<dim3(DMODEL/128, LB/64, 3*8), 256>>>(
            tgt, DMODEL,0, W, DMODEL,DD, (const float*)0,0,
            part, DMODEL, 0, LB, DMODEL, DMODEL, 8, 1.0f, 0);
        reduce_sk<<<(3*LB*DMODEL)/256, 256>>>(part, qkv, DMODEL, LB*DMODEL, LB, DMODEL, 8,
                                              Bi, DMODEL, 0);
        flash_attn<<<dim3(4, QT, BNH), 128, FSMEM>>>(q, k, v, part, partl,
                                                     LDQ, 4, 64, 1, qscale);
        flash_combine<<<BNH*QT, 256>>>(part, partl, ao, LDQ, 4);
        wgemm_nt<<<dim3(DMODEL/128, LB/64, 8), 256>>>(
            ao, DMODEL,0, W+3*DD, DMODEL,0, (const float*)0,0,
            part, DMODEL, 0, LB, DMODEL, DMODEL, 8, 1.0f, 0);
        reduce_ln<<<LB, DMODEL>>>(part, 8, Bi+3*DMODEL, tgt,
                                  ln_g + (size_t)(i*3+0)*DMODEL, ln_b + (size_t)(i*3+0)*DMODEL);

        // ---- cross-attention ----
        const float* Wc = ca_w + (size_t)i*4*DD;
        const float* Bc = ca_b + (size_t)i*4*DMODEL;
        bf16* ckp = ckvb + (size_t)i*CKV_L;
        bf16* cvp = ckp + (size_t)SBR*DMODEL;
        wgemm_nt<<<dim3(DMODEL/128, LB/64, 8), 256>>>(
            tgt, DMODEL,0, Wc, DMODEL,0, (const float*)0,0,
            part, DMODEL, 0, LB, DMODEL, DMODEL, 8, 1.0f, 0);
        reduce_sk<<<(LB*DMODEL)/256, 256>>>(part, q, DMODEL, 0, LB, DMODEL, 8,
                                            Bc, 0, 0);
        cudaStreamWaitEvent(0, evCkv[i], 0);
        flash_attn_bf<<<dim3(16, QT, BNH), 128, FSMEM>>>(q, ckp, cvp, CKVB_PL,
                                                         part, partl, LDQ, 16, 512, qscale);
        flash_combine<<<BNH*QT, 256>>>(part, partl, ao, LDQ, 16);
        wgemm_nt<<<dim3(DMODEL/128, LB/64, 8), 256>>>(
            ao, DMODEL,0, Wc+3*DD, DMODEL,0, (const float*)0,0,
            part, DMODEL, 0, LB, DMODEL, DMODEL, 8, 1.0f, 0);
        reduce_ln<<<LB, DMODEL>>>(part, 8, Bc+3*DMODEL, tgt,
                                  ln_g + (size_t)(i*3+1)*DMODEL, ln_b + (size_t)(i*3+1)*DMODEL);

        // ---- FFN ----
        wgemm_nt<<<dim3(DFF/128, LB/64, 1), 256>>>(
            tgt, DMODEL,0, ff_w1 + (size_t)i*DFF*DMODEL, DMODEL,0,
            ff_b1 + (size_t)i*DFF, 0,
            ffh, DFF, 0, LB, DFF, DMODEL, 1, 1.0f, 1);
        wgemm_nt<<<dim3(DMODEL/128, LB/64, 8), 256>>>(
            ffh, DFF,0, ff_w2 + (size_t)i*DMODEL*DFF, DFF,0, (const float*)0,0,
            part, DMODEL, 0, LB, DMODEL, DFF, 8, 1.0f, 0);
        reduce_ln<<<LB, DMODEL>>>(part, 8, ff_b2 + (size_t)i*DMODEL, tgt,
                                  ln_g + (size_t)(i*3+2)*DMODEL, ln_b + (size_t)(i*3+2)*DMODEL);
    }

    // final vocab projection -> d_out [L,B,V]
    gemm_nt<<<dim3((VOCAB+63)/64, LB/64), 256>>>(tgt, DMODEL, out_w, DMODEL, out_b,
                                                 out, VOCAB, LB, VOCAB, DMODEL);
}